// round 13
// baseline (speedup 1.0000x reference)
#include <cuda_runtime.h>
#include <cuda_fp16.h>
#include <math.h>
#include <stdint.h>

#define NV   73728
#define CD   192
#define HD   8
#define DHD  24
#define FF   384
#define SETN 2048
#define SETK 36
#define NLAYER 8

// ================= helpers =================
__device__ __forceinline__ uint32_t smem_u32(const void* p) {
    uint32_t a;
    asm("{ .reg .u64 t; cvta.to.shared.u64 t, %1; cvt.u32.u64 %0, t; }" : "=r"(a) : "l"(p));
    return a;
}
__device__ __forceinline__ void cp_async16(uint32_t saddr, const void* gaddr) {
    asm volatile("cp.async.cg.shared.global [%0], [%1], 16;" :: "r"(saddr), "l"(gaddr) : "memory");
}
__device__ __forceinline__ void cp_commit() {
    asm volatile("cp.async.commit_group;" ::: "memory");
}
__device__ __forceinline__ void ldsm4(uint32_t* r, uint32_t a) {
    asm volatile("ldmatrix.sync.aligned.m8n8.x4.shared.b16 {%0,%1,%2,%3}, [%4];"
        : "=r"(r[0]), "=r"(r[1]), "=r"(r[2]), "=r"(r[3]) : "r"(a));
}
__device__ __forceinline__ void mma16816h(float* c, const uint32_t* a, uint32_t b0, uint32_t b1) {
    asm volatile("mma.sync.aligned.m16n8k16.row.col.f32.f16.f16.f32 "
        "{%0,%1,%2,%3}, {%4,%5,%6,%7}, {%8,%9}, {%0,%1,%2,%3};"
        : "+f"(c[0]), "+f"(c[1]), "+f"(c[2]), "+f"(c[3])
        : "r"(a[0]), "r"(a[1]), "r"(a[2]), "r"(a[3]), "r"(b0), "r"(b1));
}
__device__ __forceinline__ unsigned short h16(float x) {
    __half hb = __float2half_rn(x);
    return *reinterpret_cast<unsigned short*>(&hb);
}
__device__ __forceinline__ float2 h2f2(uint32_t bits) {
    __half2 h = *reinterpret_cast<__half2*>(&bits);
    return __half22float2(h);
}
__device__ __forceinline__ float gelu_f(float x) {
    return 0.5f * x * (1.0f + erff(x * 0.70710678118654752440f));
}

// ================= scratch =================
__device__ float g_X  [NV*CD];
__device__ float g_X1 [NV*CD];
__device__ float g_R  [NV*CD];
__device__ int   g_INV[4*NV];
__device__ __half g_QKVh[NV*3*CD];
__device__ __half g_FOf[NV*CD];
__device__ __half g_Gf [NV*CD];
__device__ __half g_Qf [NV*CD];
__device__ __half g_AOf[NV*CD];
__device__ __half g_X1f[NV*CD];
__device__ __half g_Hf [NV*FF];
#define W0SZ (NLAYER*3*CD*CD)
#define W1SZ (NLAYER*CD*CD)
#define W2SZ (NLAYER*FF*CD)
#define W3SZ (NLAYER*CD*FF)
__device__ __half g_W0[W0SZ];
__device__ __half g_W1[W1SZ];
__device__ __half g_W2[W2SZ];
__device__ __half g_W3[W3SZ];

// ================= inverse permutations =================
__global__ void invperm_k(const int* __restrict__ svi, int* __restrict__ inv) {
    int i = blockIdx.x * 256 + threadIdx.x;
    if (i >= 4 * NV) return;
    int t = i / NV, p = i - t * NV;
    inv[t * NV + svi[i]] = p;
}

// ================= weight conversion: single fp16 =================
__global__ void convw_k(const float* __restrict__ w0, const float* __restrict__ w1,
                        const float* __restrict__ w2, const float* __restrict__ w3,
                        __half* __restrict__ o0, __half* __restrict__ o1,
                        __half* __restrict__ o2, __half* __restrict__ o3) {
    int i = blockIdx.x * 256 + threadIdx.x;
    if (i < W0SZ) {
        o0[i] = __float2half_rn(w0[i]);
    } else if (i < W0SZ + W1SZ) {
        int j = i - W0SZ; o1[j] = __float2half_rn(w1[j]);
    } else if (i < W0SZ + W1SZ + W2SZ) {
        int j = i - W0SZ - W1SZ; o2[j] = __float2half_rn(w2[j]);
    } else if (i < W0SZ + W1SZ + W2SZ + W3SZ) {
        int j = i - W0SZ - W1SZ - W2SZ; o3[j] = __float2half_rn(w3[j]);
    }
}

// ================= layer-0 gather -> fp16 =================
__global__ void gather_k(const float* __restrict__ X, const float* __restrict__ pos,
                         const int* __restrict__ inds,
                         __half* __restrict__ Gf, __half* __restrict__ Qf) {
    int e = blockIdx.x * 256 + threadIdx.x;
    const int C4 = CD / 4;
    if (e >= NV * C4) return;
    int row = e / C4, c4 = e - row * C4;
    int vox = inds[row];
    float4 x = reinterpret_cast<const float4*>(X)[(size_t)vox * C4 + c4];
    float4 p = reinterpret_cast<const float4*>(pos)[(size_t)vox * C4 + c4];
    uint2 g = make_uint2((uint32_t)h16(x.x) | ((uint32_t)h16(x.y) << 16),
                         (uint32_t)h16(x.z) | ((uint32_t)h16(x.w) << 16));
    uint2 q = make_uint2((uint32_t)h16(x.x + p.x) | ((uint32_t)h16(x.y + p.y) << 16),
                         (uint32_t)h16(x.z + p.z) | ((uint32_t)h16(x.w + p.w) << 16));
    reinterpret_cast<uint2*>(Gf)[(size_t)row * C4 + c4] = g;
    reinterpret_cast<uint2*>(Qf)[(size_t)row * C4 + c4] = q;
}

// ================= fp16 mma GEMM, 128x64 tile (R7 config) =================
template<int EPI>
__global__ void __launch_bounds__(256, 4)
gemm_mma(const __half* __restrict__ A0, const __half* __restrict__ A1, int a1ColStart,
         const __half* __restrict__ B, const float* __restrict__ bias,
         __half* __restrict__ outH, const int* __restrict__ scatter, int Nn, int K) {
    extern __shared__ char smem[];
    const int BUF = 24576;
    const int OF_A = 0, OF_B = 16384;
    uint32_t sb = smem_u32(smem);
    int tid = threadIdx.x, wid = tid >> 5, lane = tid & 31;
    int n0 = blockIdx.x * 64, m0 = blockIdx.y * 128;
    int wm = wid & 3, wn = wid >> 2;
    const __half* __restrict__ A = (n0 >= a1ColStart) ? A1 : A0;

    int arow[4], acol[4]; uint32_t asf[4];
    int brow[2], bcol[2]; uint32_t bsf[2];
    #pragma unroll
    for (int i = 0; i < 4; i++) {
        int c = tid + (i << 8); int r = c >> 3, c8 = c & 7;
        arow[i] = r; acol[i] = c8 * 8;
        asf[i] = (uint32_t)(r * 128 + ((c8 * 16) ^ ((r & 7) << 4)));
    }
    #pragma unroll
    for (int i = 0; i < 2; i++) {
        int c = tid + (i << 8); int r = c >> 3, c8 = c & 7;
        brow[i] = r; bcol[i] = c8 * 8;
        bsf[i] = (uint32_t)(r * 128 + ((c8 * 16) ^ ((r & 7) << 4)));
    }

    int nstages = K >> 6;
    {
        #pragma unroll
        for (int i = 0; i < 4; i++)
            cp_async16(sb + OF_A + asf[i], A + (size_t)(m0 + arow[i]) * K + acol[i]);
        #pragma unroll
        for (int i = 0; i < 2; i++)
            cp_async16(sb + OF_B + bsf[i], B + (size_t)(n0 + brow[i]) * K + bcol[i]);
        cp_commit();
    }

    float acc[2][4][4] = {};
    int q = lane >> 3, j = lane & 7;

    for (int s = 0; s < nstages; s++) {
        asm volatile("cp.async.wait_group 0;" ::: "memory");
        __syncthreads();
        if (s + 1 < nstages) {
            uint32_t base = sb + ((s + 1) & 1) * BUF;
            int koff = (s + 1) * 64;
            #pragma unroll
            for (int i = 0; i < 4; i++)
                cp_async16(base + OF_A + asf[i], A + (size_t)(m0 + arow[i]) * K + koff + acol[i]);
            #pragma unroll
            for (int i = 0; i < 2; i++)
                cp_async16(base + OF_B + bsf[i], B + (size_t)(n0 + brow[i]) * K + koff + bcol[i]);
            cp_commit();
        }
        uint32_t base = sb + (s & 1) * BUF;

        #pragma unroll
        for (int kc = 0; kc < 4; kc++) {
            uint32_t af[2][4], bf[2][4];
            #pragma unroll
            for (int mt = 0; mt < 2; mt++) {
                int row = wm * 32 + mt * 16 + (q & 1) * 8 + j;
                int cb = kc * 32 + (q >> 1) * 16;
                uint32_t so = (uint32_t)(row * 128 + (cb ^ ((row & 7) << 4)));
                ldsm4(af[mt], base + OF_A + so);
            }
            #pragma unroll
            for (int np = 0; np < 2; np++) {
                int row = wn * 32 + np * 16 + (q >> 1) * 8 + j;
                int cb = kc * 32 + (q & 1) * 16;
                uint32_t so = (uint32_t)(row * 128 + (cb ^ ((row & 7) << 4)));
                ldsm4(bf[np], base + OF_B + so);
            }
            #pragma unroll
            for (int mt = 0; mt < 2; mt++) {
                #pragma unroll
                for (int nt = 0; nt < 4; nt++) {
                    uint32_t b0 = bf[nt >> 1][(nt & 1) * 2], b1 = bf[nt >> 1][(nt & 1) * 2 + 1];
                    mma16816h(acc[mt][nt], af[mt], b0, b1);
                }
            }
        }
    }

    int r4 = lane >> 2, cg = (lane & 3) * 2;
    #pragma unroll
    for (int mt = 0; mt < 2; mt++) {
        int mrow0 = m0 + wm * 32 + mt * 16 + r4;
        int mrow1 = mrow0 + 8;
        int o0 = scatter ? scatter[mrow0] : mrow0;
        int o1 = scatter ? scatter[mrow1] : mrow1;
        #pragma unroll
        for (int nt = 0; nt < 4; nt++) {
            int col = n0 + wn * 32 + nt * 8 + cg;
            float b0 = bias[col], b1 = bias[col + 1];
            float v00 = acc[mt][nt][0] + b0, v01 = acc[mt][nt][1] + b1;
            float v10 = acc[mt][nt][2] + b0, v11 = acc[mt][nt][3] + b1;
            if (EPI == 1) { v00 = gelu_f(v00); v01 = gelu_f(v01); v10 = gelu_f(v10); v11 = gelu_f(v11); }
            *reinterpret_cast<uint32_t*>(outH + (size_t)o0 * Nn + col) =
                (uint32_t)h16(v00) | ((uint32_t)h16(v01) << 16);
            *reinterpret_cast<uint32_t*>(outH + (size_t)o1 * Nn + col) =
                (uint32_t)h16(v10) | ((uint32_t)h16(v11) << 16);
        }
    }
}

// ========= fused out-proj GEMM (64x192 tile) + add + LayerNorm epilogue =========
__global__ void __launch_bounds__(256, 2)
gemm_oproj_ln(const __half* __restrict__ A, const __half* __restrict__ B,
              const float* __restrict__ bias, const int* __restrict__ inds,
              const float* __restrict__ X,
              const float* __restrict__ lng, const float* __restrict__ lnb,
              float* __restrict__ X1, __half* __restrict__ X1f) {
    extern __shared__ char smem[];
    const int BUF = 32768;
    const int OF_A = 0, OF_B = 8192;
    uint32_t sb = smem_u32(smem);
    int tid = threadIdx.x, wid = tid >> 5, lane = tid & 31;
    int m0 = blockIdx.x * 64;
    int gq = wid >> 1, wn = wid & 1;

    const int K = CD;
    const int nstages = 3;

    {
        #pragma unroll
        for (int i = 0; i < 2; i++) {
            int c = tid + (i << 8); int r = c >> 3, c8 = c & 7;
            uint32_t sf = (uint32_t)(r * 128 + ((c8 * 16) ^ ((r & 7) << 4)));
            cp_async16(sb + OF_A + sf, A + (size_t)(m0 + r) * K + c8 * 8);
        }
        #pragma unroll
        for (int i = 0; i < 6; i++) {
            int c = tid + (i << 8); int r = c >> 3, c8 = c & 7;
            uint32_t sf = (uint32_t)(r * 128 + ((c8 * 16) ^ ((r & 7) << 4)));
            cp_async16(sb + OF_B + sf, B + (size_t)r * K + c8 * 8);
        }
        cp_commit();
    }

    float acc[12][4] = {};
    int q = lane >> 3, j = lane & 7;

    for (int s = 0; s < nstages; s++) {
        asm volatile("cp.async.wait_group 0;" ::: "memory");
        __syncthreads();
        if (s + 1 < nstages) {
            uint32_t base = sb + ((s + 1) & 1) * BUF;
            int koff = (s + 1) * 64;
            #pragma unroll
            for (int i = 0; i < 2; i++) {
                int c = tid + (i << 8); int r = c >> 3, c8 = c & 7;
                uint32_t sf = (uint32_t)(r * 128 + ((c8 * 16) ^ ((r & 7) << 4)));
                cp_async16(base + OF_A + sf, A + (size_t)(m0 + r) * K + koff + c8 * 8);
            }
            #pragma unroll
            for (int i = 0; i < 6; i++) {
                int c = tid + (i << 8); int r = c >> 3, c8 = c & 7;
                uint32_t sf = (uint32_t)(r * 128 + ((c8 * 16) ^ ((r & 7) << 4)));
                cp_async16(base + OF_B + sf, B + (size_t)r * K + koff + c8 * 8);
            }
            cp_commit();
        }
        uint32_t base = sb + (s & 1) * BUF;

        #pragma unroll
        for (int kc = 0; kc < 4; kc++) {
            uint32_t af[4];
            {
                int row = gq * 16 + (q & 1) * 8 + j;
                int cb = kc * 32 + (q >> 1) * 16;
                uint32_t so = (uint32_t)(row * 128 + (cb ^ ((row & 7) << 4)));
                ldsm4(af, base + OF_A + so);
            }
            #pragma unroll
            for (int np = 0; np < 6; np++) {
                uint32_t bf[4];
                int row = wn * 96 + np * 16 + (q >> 1) * 8 + j;
                int cb = kc * 32 + (q & 1) * 16;
                uint32_t so = (uint32_t)(row * 128 + (cb ^ ((row & 7) << 4)));
                ldsm4(bf, base + OF_B + so);
                mma16816h(acc[np * 2 + 0], af, bf[0], bf[1]);
                mma16816h(acc[np * 2 + 1], af, bf[2], bf[3]);
            }
        }
    }

    int r4 = lane >> 2, cg = (lane & 3) * 2;
    int lrowA = gq * 16 + r4, lrowB = lrowA + 8;
    int oA = inds[m0 + lrowA], oB = inds[m0 + lrowB];

    float sA = 0.f, s2A = 0.f, sB = 0.f, s2B = 0.f;
    #pragma unroll
    for (int nt = 0; nt < 12; nt++) {
        int col = wn * 96 + nt * 8 + cg;
        float b0 = bias[col], b1 = bias[col + 1];
        float2 xA = *reinterpret_cast<const float2*>(X + (size_t)oA * CD + col);
        float2 xB = *reinterpret_cast<const float2*>(X + (size_t)oB * CD + col);
        float v0 = acc[nt][0] + b0 + xA.x, v1 = acc[nt][1] + b1 + xA.y;
        float v2 = acc[nt][2] + b0 + xB.x, v3 = acc[nt][3] + b1 + xB.y;
        acc[nt][0] = v0; acc[nt][1] = v1; acc[nt][2] = v2; acc[nt][3] = v3;
        sA += v0 + v1; s2A += v0 * v0 + v1 * v1;
        sB += v2 + v3; s2B += v2 * v2 + v3 * v3;
    }
    #pragma unroll
    for (int o = 1; o <= 2; o <<= 1) {
        sA  += __shfl_xor_sync(0xffffffffu, sA,  o);
        s2A += __shfl_xor_sync(0xffffffffu, s2A, o);
        sB  += __shfl_xor_sync(0xffffffffu, sB,  o);
        s2B += __shfl_xor_sync(0xffffffffu, s2B, o);
    }
    float* red = reinterpret_cast<float*>(smem);
    __syncthreads();
    if ((lane & 3) == 0) {
        red[(wn * 64 + lrowA) * 2 + 0] = sA;
        red[(wn * 64 + lrowA) * 2 + 1] = s2A;
        red[(wn * 64 + lrowB) * 2 + 0] = sB;
        red[(wn * 64 + lrowB) * 2 + 1] = s2B;
    }
    __syncthreads();
    float tsA  = red[lrowA * 2 + 0] + red[(64 + lrowA) * 2 + 0];
    float ts2A = red[lrowA * 2 + 1] + red[(64 + lrowA) * 2 + 1];
    float tsB  = red[lrowB * 2 + 0] + red[(64 + lrowB) * 2 + 0];
    float ts2B = red[lrowB * 2 + 1] + red[(64 + lrowB) * 2 + 1];
    float mA = tsA * (1.0f / CD), vA = ts2A * (1.0f / CD) - mA * mA;
    float mB = tsB * (1.0f / CD), vB = ts2B * (1.0f / CD) - mB * mB;
    float rA = rsqrtf(vA + 1e-5f), rB = rsqrtf(vB + 1e-5f);

    #pragma unroll
    for (int nt = 0; nt < 12; nt++) {
        int col = wn * 96 + nt * 8 + cg;
        float g0 = lng[col], g1 = lng[col + 1];
        float bb0 = lnb[col], bb1 = lnb[col + 1];
        float y0 = (acc[nt][0] - mA) * rA * g0 + bb0;
        float y1 = (acc[nt][1] - mA) * rA * g1 + bb1;
        float y2 = (acc[nt][2] - mB) * rB * g0 + bb0;
        float y3 = (acc[nt][3] - mB) * rB * g1 + bb1;
        *reinterpret_cast<float2*>(X1 + (size_t)oA * CD + col) = make_float2(y0, y1);
        *reinterpret_cast<float2*>(X1 + (size_t)oB * CD + col) = make_float2(y2, y3);
        *reinterpret_cast<uint32_t*>(X1f + (size_t)oA * CD + col) =
            (uint32_t)h16(y0) | ((uint32_t)h16(y1) << 16);
        *reinterpret_cast<uint32_t*>(X1f + (size_t)oB * CD + col) =
            (uint32_t)h16(y2) | ((uint32_t)h16(y3) << 16);
    }
}

// ===== per (set, head) attention — fp16 smem, 4x2 QK tiles, broadcast-aligned =====
#define KST 32   // halfs per smem row (64B)
__global__ void __launch_bounds__(128)
attn_k(const __half* __restrict__ QKV, __half* __restrict__ AOf) {
    int s = blockIdx.x, h = blockIdx.y;
    __shared__ __half qh[SETK][KST], kh[SETK][KST], vh[SETK][KST];
    __shared__ float sc[SETK][SETK];
    int tid = threadIdx.x;
    const __half* base = QKV + (size_t)s * SETK * (3 * CD) + h * DHD;
    // raw copy: 108 units (row, tensor), 48B each
    for (int t = tid; t < SETK * 3; t += 128) {
        int r = t / 3, w = t - r * 3;
        const uint4* src = reinterpret_cast<const uint4*>(base + r * (3 * CD) + w * CD);
        __half* dst = (w == 0) ? qh[r] : ((w == 1) ? kh[r] : vh[r]);
        uint4* d4 = reinterpret_cast<uint4*>(dst);
        d4[0] = src[0]; d4[1] = src[1]; d4[2] = src[2];
    }
    __syncthreads();
    const float scale = 0.20412414523193150818f;
    // QK: unit = (4 rows r0..r0+3) x (2 cols l0..l0+1); lanes vary lp fastest
    for (int u = tid; u < 9 * 18; u += 128) {
        int rq = u / 18, lp = u - rq * 18;
        int r0 = rq * 4, l0 = lp * 2;
        float a[4][2] = {};
        #pragma unroll
        for (int c4 = 0; c4 < 6; c4++) {
            float2 kf[2][2];
            #pragma unroll
            for (int jl = 0; jl < 2; jl++) {
                uint2 kr = *reinterpret_cast<const uint2*>(&kh[l0 + jl][c4 * 4]);
                kf[jl][0] = h2f2(kr.x);
                kf[jl][1] = h2f2(kr.y);
            }
            #pragma unroll
            for (int ir = 0; ir < 4; ir++) {
                uint2 qr = *reinterpret_cast<const uint2*>(&qh[r0 + ir][c4 * 4]);
                float2 q0 = h2f2(qr.x), q1 = h2f2(qr.y);
                #pragma unroll
                for (int jl = 0; jl < 2; jl++) {
                    float t0 = a[ir][jl];
                    t0 = fmaf(q0.x, kf[jl][0].x, t0);
                    t0 = fmaf(q0.y, kf[jl][0].y, t0);
                    t0 = fmaf(q1.x, kf[jl][1].x, t0);
                    t0 = fmaf(q1.y, kf[jl][1].y, t0);
                    a[ir][jl] = t0;
                }
            }
        }
        #pragma unroll
        for (int ir = 0; ir < 4; ir++)
            #pragma unroll
            for (int jl = 0; jl < 2; jl++)
                sc[r0 + ir][l0 + jl] = a[ir][jl] * scale;
    }
    __syncthreads();
    if (tid < SETK) {
        int r = tid;
        float4 rowv[9];
        #pragma unroll
        for (int i = 0; i < 9; i++) rowv[i] = *reinterpret_cast<const float4*>(&sc[r][i * 4]);
        float mx = -1e30f;
        #pragma unroll
        for (int i = 0; i < 9; i++)
            mx = fmaxf(mx, fmaxf(fmaxf(rowv[i].x, rowv[i].y), fmaxf(rowv[i].z, rowv[i].w)));
        float sum = 0.f;
        #pragma unroll
        for (int i = 0; i < 9; i++) {
            rowv[i].x = expf(rowv[i].x - mx); rowv[i].y = expf(rowv[i].y - mx);
            rowv[i].z = expf(rowv[i].z - mx); rowv[i].w = expf(rowv[i].w - mx);
            sum += rowv[i].x + rowv[i].y + rowv[i].z + rowv[i].w;
        }
        float inv = 1.0f / sum;
        #pragma unroll
        for (int i = 0; i < 9; i++) {
            rowv[i].x *= inv; rowv[i].y *= inv; rowv[i].z *= inv; rowv[i].w *= inv;
            *reinterpret_cast<float4*>(&sc[r][i * 4]) = rowv[i];
        }
    }
    __syncthreads();
    // AV: unit = (r, c4); all lanes share l in inner loop -> v reads 1 phase
    for (int u = tid; u < SETK * 6; u += 128) {
        int r = u / 6, c4 = u - r * 6;
        float a0 = 0.f, a1 = 0.f, a2 = 0.f, a3 = 0.f;
        #pragma unroll 4
        for (int l = 0; l < SETK; l++) {
            float w = sc[r][l];
            uint2 vr = *reinterpret_cast<const uint2*>(&vh[l][c4 * 4]);
            float2 v0 = h2f2(vr.x), v1 = h2f2(vr.y);
            a0 = fmaf(w, v0.x, a0); a1 = fmaf(w, v0.y, a1);
            a2 = fmaf(w, v1.x, a2); a3 = fmaf(w, v1.y, a3);
        }
        size_t ob = (size_t)(s * SETK + r) * CD + h * DHD + c4 * 4;
        *reinterpret_cast<uint2*>(AOf + ob) =
            make_uint2((uint32_t)h16(a0) | ((uint32_t)h16(a1) << 16),
                       (uint32_t)h16(a2) | ((uint32_t)h16(a3) << 16));
    }
}

// ================= warp LayerNorm (lane -> 6 consecutive cols) =================
__device__ __forceinline__ void warp_ln6c(float (&x)[6], const float* __restrict__ g,
                                          const float* __restrict__ b, int cbase, float (&y)[6]) {
    float s = 0.f, s2 = 0.f;
    #pragma unroll
    for (int j = 0; j < 6; j++) { s += x[j]; s2 += x[j] * x[j]; }
    #pragma unroll
    for (int o = 16; o > 0; o >>= 1) {
        s  += __shfl_xor_sync(0xffffffffu, s, o);
        s2 += __shfl_xor_sync(0xffffffffu, s2, o);
    }
    float mean = s * (1.0f / CD);
    float var  = s2 * (1.0f / CD) - mean * mean;
    float r = rsqrtf(var + 1e-5f);
    #pragma unroll
    for (int j = 0; j < 6; j++)
        y[j] = (x[j] - mean) * r * g[cbase + j] + b[cbase + j];
}
__device__ __forceinline__ void load6(const float* p, float (&x)[6]) {
    float2 a = *reinterpret_cast<const float2*>(p);
    float2 b = *reinterpret_cast<const float2*>(p + 2);
    float2 c = *reinterpret_cast<const float2*>(p + 4);
    x[0]=a.x; x[1]=a.y; x[2]=b.x; x[3]=b.y; x[4]=c.x; x[5]=c.y;
}
__device__ __forceinline__ void load6h(const __half* p, float (&x)[6]) {
    const __half2* hp = reinterpret_cast<const __half2*>(p);
    float2 a = __half22float2(hp[0]);
    float2 b = __half22float2(hp[1]);
    float2 c = __half22float2(hp[2]);
    x[0]=a.x; x[1]=a.y; x[2]=b.x; x[3]=b.y; x[4]=c.x; x[5]=c.y;
}
__device__ __forceinline__ void store6(float* p, const float (&y)[6]) {
    *reinterpret_cast<float2*>(p)     = make_float2(y[0], y[1]);
    *reinterpret_cast<float2*>(p + 2) = make_float2(y[2], y[3]);
    *reinterpret_cast<float2*>(p + 4) = make_float2(y[4], y[5]);
}
__device__ __forceinline__ void store6_h(__half* ph, const float (&y)[6]) {
    *reinterpret_cast<uint32_t*>(ph)     = (uint32_t)h16(y[0]) | ((uint32_t)h16(y[1]) << 16);
    *reinterpret_cast<uint32_t*>(ph + 2) = (uint32_t)h16(y[2]) | ((uint32_t)h16(y[3]) << 16);
    *reinterpret_cast<uint32_t*>(ph + 4) = (uint32_t)h16(y[4]) | ((uint32_t)h16(y[5]) << 16);
}

// LN chain + optional residual-save + optional fused next-layer gather
__global__ void __launch_bounds__(256)
fused_ln3_k(const float* __restrict__ X1, const __half* __restrict__ FOf,
            const float* __restrict__ ID, const float* __restrict__ RES,
            const float* __restrict__ g2, const float* __restrict__ b2,
            const float* __restrict__ ge, const float* __restrict__ be,
            const float* __restrict__ gb, const float* __restrict__ bb,
            float* __restrict__ out, float* __restrict__ Rdst,
            const float* __restrict__ posn, const int* __restrict__ invn,
            __half* __restrict__ Gf, __half* __restrict__ Qf) {
    int row = blockIdx.x * blockDim.y + threadIdx.y;
    int cbase = threadIdx.x * 6;
    size_t off = (size_t)row * CD + cbase;
    float x[6], t[6], y[6];
    load6(X1 + off, x); load6h(FOf + off, t);
    #pragma unroll
    for (int j = 0; j < 6; j++) x[j] += t[j];
    warp_ln6c(x, g2, b2, cbase, y);
    load6(ID + off, t);
    #pragma unroll
    for (int j = 0; j < 6; j++) x[j] = y[j] + t[j];
    warp_ln6c(x, ge, be, cbase, y);
    if (RES) {
        load6(RES + off, t);
        #pragma unroll
        for (int j = 0; j < 6; j++) x[j] = y[j] + t[j];
        warp_ln6c(x, gb, bb, cbase, y);
    }
    store6(out + off, y);
    if (Rdst) store6(Rdst + off, y);
    if (Gf) {
        int p = invn[row];
        size_t soff = (size_t)p * CD + cbase;
        store6_h(Gf + soff, y);
        float q[6];
        load6(posn + off, t);
        #pragma unroll
        for (int j = 0; j < 6; j++) q[j] = y[j] + t[j];
        store6_h(Qf + soff, q);
    }
}

// ================= host =================
extern "C" void kernel_launch(void* const* d_in, const int* in_sizes, int n_in,
                              void* d_out, int out_size) {
    const float* src       = (const float*)d_in[0];
    const float* pos_embed = (const float*)d_in[1];
    const int*   svi       = (const int*)  d_in[2];
    const float* in_proj_w = (const float*)d_in[4];
    const float* in_proj_b = (const float*)d_in[5];
    const float* out_w     = (const float*)d_in[6];
    const float* out_b     = (const float*)d_in[7];
    const float* lin1_w    = (const float*)d_in[8];
    const float* lin1_b    = (const float*)d_in[9];
    const float* lin2_w    = (const float*)d_in[10];
    const float* lin2_b    = (const float*)d_in[11];
    const float* ln1_g     = (const float*)d_in[12];
    const float* ln1_b     = (const float*)d_in[13];
    const float* ln2_g     = (const float*)d_in[14];
    const float* ln2_b     = (const float*)d_in[15];
    const float* enc_g     = (const float*)d_in[16];
    const float* enc_b     = (const float*)d_in[17];
    const float* blk_g     = (const float*)d_in[18];
    const float* blk_b     = (const float*)d_in[19];
    float* outp = (float*)d_out;

    float *X, *X1, *R;
    int *INV;
    __half *QKVh, *FOf, *Gf, *Qf, *AOf, *X1f, *Hf;
    __half *W0, *W1, *W2, *W3;
    cudaGetSymbolAddress((void**)&X,    g_X);    cudaGetSymbolAddress((void**)&X1,  g_X1);
    cudaGetSymbolAddress((void**)&R,    g_R);    cudaGetSymbolAddress((void**)&INV, g_INV);
    cudaGetSymbolAddress((void**)&QKVh, g_QKVh); cudaGetSymbolAddress((void**)&FOf, g_FOf);
    cudaGetSymbolAddress((void**)&Gf,   g_Gf);   cudaGetSymbolAddress((void**)&Qf,  g_Qf);
    cudaGetSymbolAddress((void**)&AOf,  g_AOf);  cudaGetSymbolAddress((void**)&X1f, g_X1f);
    cudaGetSymbolAddress((void**)&Hf,   g_Hf);
    cudaGetSymbolAddress((void**)&W0,   g_W0);   cudaGetSymbolAddress((void**)&W1,  g_W1);
    cudaGetSymbolAddress((void**)&W2,   g_W2);   cudaGetSymbolAddress((void**)&W3,  g_W3);

    const int SMEM_GEMM = 49152;
    const int SMEM_OPLN = 65536;
    cudaFuncSetAttribute(gemm_mma<0>, cudaFuncAttributeMaxDynamicSharedMemorySize, SMEM_GEMM);
    cudaFuncSetAttribute(gemm_mma<1>, cudaFuncAttributeMaxDynamicSharedMemorySize, SMEM_GEMM);
    cudaFuncSetAttribute(gemm_oproj_ln, cudaFuncAttributeMaxDynamicSharedMemorySize, SMEM_OPLN);

    const size_t NC = (size_t)NV * CD;
    cudaMemcpyAsync(X, src, NC * sizeof(float), cudaMemcpyDeviceToDevice, 0);
    cudaMemcpyAsync(R, src, NC * sizeof(float), cudaMemcpyDeviceToDevice, 0);

    int totW = W0SZ + W1SZ + W2SZ + W3SZ;
    convw_k<<<(totW + 255) / 256, 256>>>(in_proj_w, out_w, lin1_w, lin2_w, W0, W1, W2, W3);
    invperm_k<<<(4 * NV + 255) / 256, 256>>>(svi, INV);

    dim3 lnGrid(NV / 8), lnBlk(32, 8);
    int gatherBlocks = (NV * (CD / 4) + 255) / 256;

    gather_k<<<gatherBlocks, 256>>>(X, pos_embed, svi, Gf, Qf);

    for (int blk = 0; blk < 4; blk++) {
        int shift = blk & 1;
        for (int i = 0; i < 2; i++) {
            int li = blk * 2 + i;
            const int* inds = svi + (size_t)(shift * 2 + i) * SETN * SETK;

            // QKV: cols [0,384) from Q-input, cols [384,576) from G
            gemm_mma<0><<<dim3(9, 576), 256, SMEM_GEMM>>>(
                Qf, Gf, 384,
                W0 + (size_t)li * 3 * CD * CD, in_proj_b + (size_t)li * 3 * CD,
                QKVh, nullptr, 3 * CD, CD);

            attn_k<<<dim3(SETN, HD), 128>>>(QKVh, AOf);

            // out-proj + scatter + add + LN1 (fused)
            gemm_oproj_ln<<<NV / 64, 256, SMEM_OPLN>>>(
                AOf, W1 + (size_t)li * CD * CD, out_b + (size_t)li * CD,
                inds, X, ln1_g + li * CD, ln1_b + li * CD, X1, X1f);

            // ffn1 + gelu
            gemm_mma<1><<<dim3(6, 576), 256, SMEM_GEMM>>>(
                X1f, X1f, 1 << 30,
                W2 + (size_t)li * FF * CD, lin1_b + (size_t)li * FF,
                Hf, nullptr, FF, CD);

            // ffn2
            gemm_mma<0><<<dim3(3, 576), 256, SMEM_GEMM>>>(
                Hf, Hf, 1 << 30,
                W3 + (size_t)li * CD * FF, lin2_b + (size_t)li * CD,
                FOf, nullptr, CD, FF);

            bool blockEnd = (i == 1);
            bool last = (li == NLAYER - 1);
            const float* posn = nullptr; const int* invn = nullptr;
            __half *gf = nullptr, *qf = nullptr;
            if (!last) {
                int lnx = li + 1;
                int pn = ((lnx / 2) & 1) * 2 + (lnx & 1);
                posn = pos_embed + (size_t)(lnx & 1) * NC;
                invn = INV + (size_t)pn * NV;
                gf = Gf; qf = Qf;
            }
            fused_ln3_k<<<lnGrid, lnBlk>>>(
                X1, FOf, X, blockEnd ? R : nullptr,
                ln2_g + li * CD, ln2_b + li * CD,
                enc_g + li * CD, enc_b + li * CD,
                blk_g + blk * CD, blk_b + blk * CD,
                last ? outp : X,
                (blockEnd && !last) ? R : nullptr,
                posn, invn, gf, qf);
        }
    }
}

// round 14
// speedup vs baseline: 1.0416x; 1.0416x over previous
#include <cuda_runtime.h>
#include <cuda_fp16.h>
#include <math.h>
#include <stdint.h>

#define NV   73728
#define CD   192
#define HD   8
#define DHD  24
#define FF   384
#define SETN 2048
#define SETK 36
#define NLAYER 8

// ================= helpers =================
__device__ __forceinline__ uint32_t smem_u32(const void* p) {
    uint32_t a;
    asm("{ .reg .u64 t; cvta.to.shared.u64 t, %1; cvt.u32.u64 %0, t; }" : "=r"(a) : "l"(p));
    return a;
}
__device__ __forceinline__ void cp_async16(uint32_t saddr, const void* gaddr) {
    asm volatile("cp.async.cg.shared.global [%0], [%1], 16;" :: "r"(saddr), "l"(gaddr) : "memory");
}
__device__ __forceinline__ void cp_commit() {
    asm volatile("cp.async.commit_group;" ::: "memory");
}
__device__ __forceinline__ void ldsm4(uint32_t* r, uint32_t a) {
    asm volatile("ldmatrix.sync.aligned.m8n8.x4.shared.b16 {%0,%1,%2,%3}, [%4];"
        : "=r"(r[0]), "=r"(r[1]), "=r"(r[2]), "=r"(r[3]) : "r"(a));
}
__device__ __forceinline__ void mma16816h(float* c, const uint32_t* a, uint32_t b0, uint32_t b1) {
    asm volatile("mma.sync.aligned.m16n8k16.row.col.f32.f16.f16.f32 "
        "{%0,%1,%2,%3}, {%4,%5,%6,%7}, {%8,%9}, {%0,%1,%2,%3};"
        : "+f"(c[0]), "+f"(c[1]), "+f"(c[2]), "+f"(c[3])
        : "r"(a[0]), "r"(a[1]), "r"(a[2]), "r"(a[3]), "r"(b0), "r"(b1));
}
__device__ __forceinline__ unsigned short h16(float x) {
    __half hb = __float2half_rn(x);
    return *reinterpret_cast<unsigned short*>(&hb);
}
__device__ __forceinline__ float gelu_f(float x) {
    return 0.5f * x * (1.0f + erff(x * 0.70710678118654752440f));
}

// ================= scratch =================
__device__ float g_X  [NV*CD];
__device__ float g_R  [NV*CD];
__device__ int   g_INV[4*NV];
__device__ __half g_QKVh[NV*3*CD];
__device__ __half g_FOf[NV*CD];
__device__ __half g_Gf [NV*CD];
__device__ __half g_Qf [NV*CD];
__device__ __half g_AOf[NV*CD];
__device__ __half g_X1f[NV*CD];
__device__ __half g_Hf [NV*FF];
#define W0SZ (NLAYER*3*CD*CD)
#define W1SZ (NLAYER*CD*CD)
#define W2SZ (NLAYER*FF*CD)
#define W3SZ (NLAYER*CD*FF)
__device__ __half g_W0[W0SZ];
__device__ __half g_W1[W1SZ];
__device__ __half g_W2[W2SZ];
__device__ __half g_W3[W3SZ];

// ================= inverse permutations =================
__global__ void invperm_k(const int* __restrict__ svi, int* __restrict__ inv) {
    int i = blockIdx.x * 256 + threadIdx.x;
    if (i >= 4 * NV) return;
    int t = i / NV, p = i - t * NV;
    inv[t * NV + svi[i]] = p;
}

// ================= weight conversion: single fp16 =================
__global__ void convw_k(const float* __restrict__ w0, const float* __restrict__ w1,
                        const float* __restrict__ w2, const float* __restrict__ w3,
                        __half* __restrict__ o0, __half* __restrict__ o1,
                        __half* __restrict__ o2, __half* __restrict__ o3) {
    int i = blockIdx.x * 256 + threadIdx.x;
    if (i < W0SZ) {
        o0[i] = __float2half_rn(w0[i]);
    } else if (i < W0SZ + W1SZ) {
        int j = i - W0SZ; o1[j] = __float2half_rn(w1[j]);
    } else if (i < W0SZ + W1SZ + W2SZ) {
        int j = i - W0SZ - W1SZ; o2[j] = __float2half_rn(w2[j]);
    } else if (i < W0SZ + W1SZ + W2SZ + W3SZ) {
        int j = i - W0SZ - W1SZ - W2SZ; o3[j] = __float2half_rn(w3[j]);
    }
}

// ================= layer-0 gather -> fp16 =================
__global__ void gather_k(const float* __restrict__ X, const float* __restrict__ pos,
                         const int* __restrict__ inds,
                         __half* __restrict__ Gf, __half* __restrict__ Qf) {
    int e = blockIdx.x * 256 + threadIdx.x;
    const int C4 = CD / 4;
    if (e >= NV * C4) return;
    int row = e / C4, c4 = e - row * C4;
    int vox = inds[row];
    float4 x = reinterpret_cast<const float4*>(X)[(size_t)vox * C4 + c4];
    float4 p = reinterpret_cast<const float4*>(pos)[(size_t)vox * C4 + c4];
    uint2 g = make_uint2((uint32_t)h16(x.x) | ((uint32_t)h16(x.y) << 16),
                         (uint32_t)h16(x.z) | ((uint32_t)h16(x.w) << 16));
    uint2 q = make_uint2((uint32_t)h16(x.x + p.x) | ((uint32_t)h16(x.y + p.y) << 16),
                         (uint32_t)h16(x.z + p.z) | ((uint32_t)h16(x.w + p.w) << 16));
    reinterpret_cast<uint2*>(Gf)[(size_t)row * C4 + c4] = g;
    reinterpret_cast<uint2*>(Qf)[(size_t)row * C4 + c4] = q;
}

// ================= fp16 mma GEMM, 128x64 tile (R7 config) =================
template<int EPI>
__global__ void __launch_bounds__(256, 4)
gemm_mma(const __half* __restrict__ A0, const __half* __restrict__ A1, int a1ColStart,
         const __half* __restrict__ B, const float* __restrict__ bias,
         __half* __restrict__ outH, const int* __restrict__ scatter, int Nn, int K) {
    extern __shared__ char smem[];
    const int BUF = 24576;
    const int OF_A = 0, OF_B = 16384;
    uint32_t sb = smem_u32(smem);
    int tid = threadIdx.x, wid = tid >> 5, lane = tid & 31;
    int n0 = blockIdx.x * 64, m0 = blockIdx.y * 128;
    int wm = wid & 3, wn = wid >> 2;
    const __half* __restrict__ A = (n0 >= a1ColStart) ? A1 : A0;

    int arow[4], acol[4]; uint32_t asf[4];
    int brow[2], bcol[2]; uint32_t bsf[2];
    #pragma unroll
    for (int i = 0; i < 4; i++) {
        int c = tid + (i << 8); int r = c >> 3, c8 = c & 7;
        arow[i] = r; acol[i] = c8 * 8;
        asf[i] = (uint32_t)(r * 128 + ((c8 * 16) ^ ((r & 7) << 4)));
    }
    #pragma unroll
    for (int i = 0; i < 2; i++) {
        int c = tid + (i << 8); int r = c >> 3, c8 = c & 7;
        brow[i] = r; bcol[i] = c8 * 8;
        bsf[i] = (uint32_t)(r * 128 + ((c8 * 16) ^ ((r & 7) << 4)));
    }

    int nstages = K >> 6;
    {
        #pragma unroll
        for (int i = 0; i < 4; i++)
            cp_async16(sb + OF_A + asf[i], A + (size_t)(m0 + arow[i]) * K + acol[i]);
        #pragma unroll
        for (int i = 0; i < 2; i++)
            cp_async16(sb + OF_B + bsf[i], B + (size_t)(n0 + brow[i]) * K + bcol[i]);
        cp_commit();
    }

    float acc[2][4][4] = {};
    int q = lane >> 3, j = lane & 7;

    for (int s = 0; s < nstages; s++) {
        asm volatile("cp.async.wait_group 0;" ::: "memory");
        __syncthreads();
        if (s + 1 < nstages) {
            uint32_t base = sb + ((s + 1) & 1) * BUF;
            int koff = (s + 1) * 64;
            #pragma unroll
            for (int i = 0; i < 4; i++)
                cp_async16(base + OF_A + asf[i], A + (size_t)(m0 + arow[i]) * K + koff + acol[i]);
            #pragma unroll
            for (int i = 0; i < 2; i++)
                cp_async16(base + OF_B + bsf[i], B + (size_t)(n0 + brow[i]) * K + koff + bcol[i]);
            cp_commit();
        }
        uint32_t base = sb + (s & 1) * BUF;

        #pragma unroll
        for (int kc = 0; kc < 4; kc++) {
            uint32_t af[2][4], bf[2][4];
            #pragma unroll
            for (int mt = 0; mt < 2; mt++) {
                int row = wm * 32 + mt * 16 + (q & 1) * 8 + j;
                int cb = kc * 32 + (q >> 1) * 16;
                uint32_t so = (uint32_t)(row * 128 + (cb ^ ((row & 7) << 4)));
                ldsm4(af[mt], base + OF_A + so);
            }
            #pragma unroll
            for (int np = 0; np < 2; np++) {
                int row = wn * 32 + np * 16 + (q >> 1) * 8 + j;
                int cb = kc * 32 + (q & 1) * 16;
                uint32_t so = (uint32_t)(row * 128 + (cb ^ ((row & 7) << 4)));
                ldsm4(bf[np], base + OF_B + so);
            }
            #pragma unroll
            for (int mt = 0; mt < 2; mt++) {
                #pragma unroll
                for (int nt = 0; nt < 4; nt++) {
                    uint32_t b0 = bf[nt >> 1][(nt & 1) * 2], b1 = bf[nt >> 1][(nt & 1) * 2 + 1];
                    mma16816h(acc[mt][nt], af[mt], b0, b1);
                }
            }
        }
    }

    int r4 = lane >> 2, cg = (lane & 3) * 2;
    #pragma unroll
    for (int mt = 0; mt < 2; mt++) {
        int mrow0 = m0 + wm * 32 + mt * 16 + r4;
        int mrow1 = mrow0 + 8;
        int o0 = scatter ? scatter[mrow0] : mrow0;
        int o1 = scatter ? scatter[mrow1] : mrow1;
        #pragma unroll
        for (int nt = 0; nt < 4; nt++) {
            int col = n0 + wn * 32 + nt * 8 + cg;
            float b0 = bias[col], b1 = bias[col + 1];
            float v00 = acc[mt][nt][0] + b0, v01 = acc[mt][nt][1] + b1;
            float v10 = acc[mt][nt][2] + b0, v11 = acc[mt][nt][3] + b1;
            if (EPI == 1) { v00 = gelu_f(v00); v01 = gelu_f(v01); v10 = gelu_f(v10); v11 = gelu_f(v11); }
            *reinterpret_cast<uint32_t*>(outH + (size_t)o0 * Nn + col) =
                (uint32_t)h16(v00) | ((uint32_t)h16(v01) << 16);
            *reinterpret_cast<uint32_t*>(outH + (size_t)o1 * Nn + col) =
                (uint32_t)h16(v10) | ((uint32_t)h16(v11) << 16);
        }
    }
}

// ========= fused out-proj GEMM (64x192 tile) + add + LayerNorm epilogue =========
// Writes LN result only as fp16 X1f.
__global__ void __launch_bounds__(256, 2)
gemm_oproj_ln(const __half* __restrict__ A, const __half* __restrict__ B,
              const float* __restrict__ bias, const int* __restrict__ inds,
              const float* __restrict__ X,
              const float* __restrict__ lng, const float* __restrict__ lnb,
              __half* __restrict__ X1f) {
    extern __shared__ char smem[];
    const int BUF = 32768;
    const int OF_A = 0, OF_B = 8192;
    uint32_t sb = smem_u32(smem);
    int tid = threadIdx.x, wid = tid >> 5, lane = tid & 31;
    int m0 = blockIdx.x * 64;
    int gq = wid >> 1, wn = wid & 1;

    const int K = CD;
    const int nstages = 3;

    {
        #pragma unroll
        for (int i = 0; i < 2; i++) {
            int c = tid + (i << 8); int r = c >> 3, c8 = c & 7;
            uint32_t sf = (uint32_t)(r * 128 + ((c8 * 16) ^ ((r & 7) << 4)));
            cp_async16(sb + OF_A + sf, A + (size_t)(m0 + r) * K + c8 * 8);
        }
        #pragma unroll
        for (int i = 0; i < 6; i++) {
            int c = tid + (i << 8); int r = c >> 3, c8 = c & 7;
            uint32_t sf = (uint32_t)(r * 128 + ((c8 * 16) ^ ((r & 7) << 4)));
            cp_async16(sb + OF_B + sf, B + (size_t)r * K + c8 * 8);
        }
        cp_commit();
    }

    float acc[12][4] = {};
    int q = lane >> 3, j = lane & 7;

    for (int s = 0; s < nstages; s++) {
        asm volatile("cp.async.wait_group 0;" ::: "memory");
        __syncthreads();
        if (s + 1 < nstages) {
            uint32_t base = sb + ((s + 1) & 1) * BUF;
            int koff = (s + 1) * 64;
            #pragma unroll
            for (int i = 0; i < 2; i++) {
                int c = tid + (i << 8); int r = c >> 3, c8 = c & 7;
                uint32_t sf = (uint32_t)(r * 128 + ((c8 * 16) ^ ((r & 7) << 4)));
                cp_async16(base + OF_A + sf, A + (size_t)(m0 + r) * K + koff + c8 * 8);
            }
            #pragma unroll
            for (int i = 0; i < 6; i++) {
                int c = tid + (i << 8); int r = c >> 3, c8 = c & 7;
                uint32_t sf = (uint32_t)(r * 128 + ((c8 * 16) ^ ((r & 7) << 4)));
                cp_async16(base + OF_B + sf, B + (size_t)r * K + koff + c8 * 8);
            }
            cp_commit();
        }
        uint32_t base = sb + (s & 1) * BUF;

        #pragma unroll
        for (int kc = 0; kc < 4; kc++) {
            uint32_t af[4];
            {
                int row = gq * 16 + (q & 1) * 8 + j;
                int cb = kc * 32 + (q >> 1) * 16;
                uint32_t so = (uint32_t)(row * 128 + (cb ^ ((row & 7) << 4)));
                ldsm4(af, base + OF_A + so);
            }
            #pragma unroll
            for (int np = 0; np < 6; np++) {
                uint32_t bf[4];
                int row = wn * 96 + np * 16 + (q >> 1) * 8 + j;
                int cb = kc * 32 + (q & 1) * 16;
                uint32_t so = (uint32_t)(row * 128 + (cb ^ ((row & 7) << 4)));
                ldsm4(bf, base + OF_B + so);
                mma16816h(acc[np * 2 + 0], af, bf[0], bf[1]);
                mma16816h(acc[np * 2 + 1], af, bf[2], bf[3]);
            }
        }
    }

    int r4 = lane >> 2, cg = (lane & 3) * 2;
    int lrowA = gq * 16 + r4, lrowB = lrowA + 8;
    int oA = inds[m0 + lrowA], oB = inds[m0 + lrowB];

    float sA = 0.f, s2A = 0.f, sB = 0.f, s2B = 0.f;
    #pragma unroll
    for (int nt = 0; nt < 12; nt++) {
        int col = wn * 96 + nt * 8 + cg;
        float b0 = bias[col], b1 = bias[col + 1];
        float2 xA = *reinterpret_cast<const float2*>(X + (size_t)oA * CD + col);
        float2 xB = *reinterpret_cast<const float2*>(X + (size_t)oB * CD + col);
        float v0 = acc[nt][0] + b0 + xA.x, v1 = acc[nt][1] + b1 + xA.y;
        float v2 = acc[nt][2] + b0 + xB.x, v3 = acc[nt][3] + b1 + xB.y;
        acc[nt][0] = v0; acc[nt][1] = v1; acc[nt][2] = v2; acc[nt][3] = v3;
        sA += v0 + v1; s2A += v0 * v0 + v1 * v1;
        sB += v2 + v3; s2B += v2 * v2 + v3 * v3;
    }
    #pragma unroll
    for (int o = 1; o <= 2; o <<= 1) {
        sA  += __shfl_xor_sync(0xffffffffu, sA,  o);
        s2A += __shfl_xor_sync(0xffffffffu, s2A, o);
        sB  += __shfl_xor_sync(0xffffffffu, sB,  o);
        s2B += __shfl_xor_sync(0xffffffffu, s2B, o);
    }
    float* red = reinterpret_cast<float*>(smem);
    __syncthreads();
    if ((lane & 3) == 0) {
        red[(wn * 64 + lrowA) * 2 + 0] = sA;
        red[(wn * 64 + lrowA) * 2 + 1] = s2A;
        red[(wn * 64 + lrowB) * 2 + 0] = sB;
        red[(wn * 64 + lrowB) * 2 + 1] = s2B;
    }
    __syncthreads();
    float tsA  = red[lrowA * 2 + 0] + red[(64 + lrowA) * 2 + 0];
    float ts2A = red[lrowA * 2 + 1] + red[(64 + lrowA) * 2 + 1];
    float tsB  = red[lrowB * 2 + 0] + red[(64 + lrowB) * 2 + 0];
    float ts2B = red[lrowB * 2 + 1] + red[(64 + lrowB) * 2 + 1];
    float mA = tsA * (1.0f / CD), vA = ts2A * (1.0f / CD) - mA * mA;
    float mB = tsB * (1.0f / CD), vB = ts2B * (1.0f / CD) - mB * mB;
    float rA = rsqrtf(vA + 1e-5f), rB = rsqrtf(vB + 1e-5f);

    #pragma unroll
    for (int nt = 0; nt < 12; nt++) {
        int col = wn * 96 + nt * 8 + cg;
        float g0 = lng[col], g1 = lng[col + 1];
        float bb0 = lnb[col], bb1 = lnb[col + 1];
        float y0 = (acc[nt][0] - mA) * rA * g0 + bb0;
        float y1 = (acc[nt][1] - mA) * rA * g1 + bb1;
        float y2 = (acc[nt][2] - mB) * rB * g0 + bb0;
        float y3 = (acc[nt][3] - mB) * rB * g1 + bb1;
        *reinterpret_cast<uint32_t*>(X1f + (size_t)oA * CD + col) =
            (uint32_t)h16(y0) | ((uint32_t)h16(y1) << 16);
        *reinterpret_cast<uint32_t*>(X1f + (size_t)oB * CD + col) =
            (uint32_t)h16(y2) | ((uint32_t)h16(y3) << 16);
    }
}

// ===== per (set, head) attention — R12 version (4r x 1l broadcast QK) =====
#define DP 28
__global__ void __launch_bounds__(128)
attn_k(const __half* __restrict__ QKV, __half* __restrict__ AOf) {
    int s = blockIdx.x, h = blockIdx.y;
    __shared__ float q[SETK][DP], k[SETK][DP], v[SETK][DP];
    __shared__ float sc[SETK][SETK];
    int tid = threadIdx.x;
    const __half* base = QKV + (size_t)s * SETK * (3 * CD) + h * DHD;
    for (int t = tid; t < SETK * 6; t += 128) {
        int r = t / 6, c4 = t - r * 6;
        const __half* rp = base + r * (3 * CD) + c4 * 4;
        const __half2* qp = reinterpret_cast<const __half2*>(rp);
        const __half2* kp = reinterpret_cast<const __half2*>(rp + CD);
        const __half2* vp = reinterpret_cast<const __half2*>(rp + 2 * CD);
        float2 a0 = __half22float2(qp[0]), a1 = __half22float2(qp[1]);
        q[r][c4*4+0] = a0.x; q[r][c4*4+1] = a0.y; q[r][c4*4+2] = a1.x; q[r][c4*4+3] = a1.y;
        float2 b0 = __half22float2(kp[0]), b1 = __half22float2(kp[1]);
        k[r][c4*4+0] = b0.x; k[r][c4*4+1] = b0.y; k[r][c4*4+2] = b1.x; k[r][c4*4+3] = b1.y;
        float2 c0 = __half22float2(vp[0]), c1 = __half22float2(vp[1]);
        v[r][c4*4+0] = c0.x; v[r][c4*4+1] = c0.y; v[r][c4*4+2] = c1.x; v[r][c4*4+3] = c1.y;
    }
    __syncthreads();
    const float scale = 0.20412414523193150818f;
    for (int u = tid; u < 9 * SETK; u += 128) {
        int rq = u / SETK, l = u - rq * SETK;
        int r0 = rq * 4;
        float a0 = 0.f, a1 = 0.f, a2 = 0.f, a3 = 0.f;
        #pragma unroll
        for (int c4 = 0; c4 < 6; c4++) {
            float4 b  = *reinterpret_cast<const float4*>(&k[l][c4 * 4]);
            float4 q0 = *reinterpret_cast<const float4*>(&q[r0 + 0][c4 * 4]);
            float4 q1 = *reinterpret_cast<const float4*>(&q[r0 + 1][c4 * 4]);
            float4 q2 = *reinterpret_cast<const float4*>(&q[r0 + 2][c4 * 4]);
            float4 q3 = *reinterpret_cast<const float4*>(&q[r0 + 3][c4 * 4]);
            a0 = fmaf(q0.x, b.x, a0); a0 = fmaf(q0.y, b.y, a0);
            a0 = fmaf(q0.z, b.z, a0); a0 = fmaf(q0.w, b.w, a0);
            a1 = fmaf(q1.x, b.x, a1); a1 = fmaf(q1.y, b.y, a1);
            a1 = fmaf(q1.z, b.z, a1); a1 = fmaf(q1.w, b.w, a1);
            a2 = fmaf(q2.x, b.x, a2); a2 = fmaf(q2.y, b.y, a2);
            a2 = fmaf(q2.z, b.z, a2); a2 = fmaf(q2.w, b.w, a2);
            a3 = fmaf(q3.x, b.x, a3); a3 = fmaf(q3.y, b.y, a3);
            a3 = fmaf(q3.z, b.z, a3); a3 = fmaf(q3.w, b.w, a3);
        }
        sc[r0 + 0][l] = a0 * scale;
        sc[r0 + 1][l] = a1 * scale;
        sc[r0 + 2][l] = a2 * scale;
        sc[r0 + 3][l] = a3 * scale;
    }
    __syncthreads();
    if (tid < SETK) {
        int r = tid;
        float4 rowv[9];
        #pragma unroll
        for (int i = 0; i < 9; i++) rowv[i] = *reinterpret_cast<const float4*>(&sc[r][i * 4]);
        float mx = -1e30f;
        #pragma unroll
        for (int i = 0; i < 9; i++)
            mx = fmaxf(mx, fmaxf(fmaxf(rowv[i].x, rowv[i].y), fmaxf(rowv[i].z, rowv[i].w)));
        float sum = 0.f;
        #pragma unroll
        for (int i = 0; i < 9; i++) {
            rowv[i].x = expf(rowv[i].x - mx); rowv[i].y = expf(rowv[i].y - mx);
            rowv[i].z = expf(rowv[i].z - mx); rowv[i].w = expf(rowv[i].w - mx);
            sum += rowv[i].x + rowv[i].y + rowv[i].z + rowv[i].w;
        }
        float inv = 1.0f / sum;
        #pragma unroll
        for (int i = 0; i < 9; i++) {
            rowv[i].x *= inv; rowv[i].y *= inv; rowv[i].z *= inv; rowv[i].w *= inv;
            *reinterpret_cast<float4*>(&sc[r][i * 4]) = rowv[i];
        }
    }
    __syncthreads();
    for (int u = tid; u < SETK * 6; u += 128) {
        int r = u / 6, c4 = u - r * 6;
        float4 acc = make_float4(0.f, 0.f, 0.f, 0.f);
        #pragma unroll 4
        for (int l = 0; l < SETK; l++) {
            float w = sc[r][l];
            float4 vv = *reinterpret_cast<const float4*>(&v[l][c4 * 4]);
            acc.x = fmaf(w, vv.x, acc.x); acc.y = fmaf(w, vv.y, acc.y);
            acc.z = fmaf(w, vv.z, acc.z); acc.w = fmaf(w, vv.w, acc.w);
        }
        size_t ob = (size_t)(s * SETK + r) * CD + h * DHD + c4 * 4;
        *reinterpret_cast<uint2*>(AOf + ob) =
            make_uint2((uint32_t)h16(acc.x) | ((uint32_t)h16(acc.y) << 16),
                       (uint32_t)h16(acc.z) | ((uint32_t)h16(acc.w) << 16));
    }
}

// ================= warp LayerNorm (lane -> 6 consecutive cols) =================
__device__ __forceinline__ void warp_ln6c(float (&x)[6], const float* __restrict__ g,
                                          const float* __restrict__ b, int cbase, float (&y)[6]) {
    float s = 0.f, s2 = 0.f;
    #pragma unroll
    for (int j = 0; j < 6; j++) { s += x[j]; s2 += x[j] * x[j]; }
    #pragma unroll
    for (int o = 16; o > 0; o >>= 1) {
        s  += __shfl_xor_sync(0xffffffffu, s, o);
        s2 += __shfl_xor_sync(0xffffffffu, s2, o);
    }
    float mean = s * (1.0f / CD);
    float var  = s2 * (1.0f / CD) - mean * mean;
    float r = rsqrtf(var + 1e-5f);
    #pragma unroll
    for (int j = 0; j < 6; j++)
        y[j] = (x[j] - mean) * r * g[cbase + j] + b[cbase + j];
}
__device__ __forceinline__ void load6(const float* p, float (&x)[6]) {
    float2 a = *reinterpret_cast<const float2*>(p);
    float2 b = *reinterpret_cast<const float2*>(p + 2);
    float2 c = *reinterpret_cast<const float2*>(p + 4);
    x[0]=a.x; x[1]=a.y; x[2]=b.x; x[3]=b.y; x[4]=c.x; x[5]=c.y;
}
__device__ __forceinline__ void load6h(const __half* p, float (&x)[6]) {
    const __half2* hp = reinterpret_cast<const __half2*>(p);
    float2 a = __half22float2(hp[0]);
    float2 b = __half22float2(hp[1]);
    float2 c = __half22float2(hp[2]);
    x[0]=a.x; x[1]=a.y; x[2]=b.x; x[3]=b.y; x[4]=c.x; x[5]=c.y;
}
__device__ __forceinline__ void store6(float* p, const float (&y)[6]) {
    *reinterpret_cast<float2*>(p)     = make_float2(y[0], y[1]);
    *reinterpret_cast<float2*>(p + 2) = make_float2(y[2], y[3]);
    *reinterpret_cast<float2*>(p + 4) = make_float2(y[4], y[5]);
}
__device__ __forceinline__ void store6_h(__half* ph, const float (&y)[6]) {
    *reinterpret_cast<uint32_t*>(ph)     = (uint32_t)h16(y[0]) | ((uint32_t)h16(y[1]) << 16);
    *reinterpret_cast<uint32_t*>(ph + 2) = (uint32_t)h16(y[2]) | ((uint32_t)h16(y[3]) << 16);
    *reinterpret_cast<uint32_t*>(ph + 4) = (uint32_t)h16(y[4]) | ((uint32_t)h16(y[5]) << 16);
}

// LN chain: reads X1f (fp16) + FOf (fp16) + fp32 ID/RES
__global__ void __launch_bounds__(256)
fused_ln3_k(const __half* __restrict__ X1f, const __half* __restrict__ FOf,
            const float* __restrict__ ID, const float* __restrict__ RES,
            const float* __restrict__ g2, const float* __restrict__ b2,
            const float* __restrict__ ge, const float* __restrict__ be,
            const float* __restrict__ gb, const float* __restrict__ bb,
            float* __restrict__ out, float* __restrict__ Rdst,
            const float* __restrict__ posn, const int* __restrict__ invn,
            __half* __restrict__ Gf, __half* __restrict__ Qf) {
    int row = blockIdx.x * blockDim.y + threadIdx.y;
    int cbase = threadIdx.x * 6;
    size_t off = (size_t)row * CD + cbase;
    float x[6], t[6], y[6];
    load6h(X1f + off, x); load6h(FOf + off, t);
    #pragma unroll
    for (int j = 0; j < 6; j++) x[j] += t[j];
    warp_ln6c(x, g2, b2, cbase, y);
    load6(ID + off, t);
    #pragma unroll
    for (int j = 0; j < 6; j++) x[j] = y[j] + t[j];
    warp_ln6c(x, ge, be, cbase, y);
    if (RES) {
        load6(RES + off, t);
        #pragma unroll
        for (int j = 0; j < 6; j++) x[j] = y[j] + t[j];
        warp_ln6c(x, gb, bb, cbase, y);
    }
    store6(out + off, y);
    if (Rdst) store6(Rdst + off, y);
    if (Gf) {
        int p = invn[row];
        size_t soff = (size_t)p * CD + cbase;
        store6_h(Gf + soff, y);
        float q[6];
        load6(posn + off, t);
        #pragma unroll
        for (int j = 0; j < 6; j++) q[j] = y[j] + t[j];
        store6_h(Qf + soff, q);
    }
}

// ================= host =================
extern "C" void kernel_launch(void* const* d_in, const int* in_sizes, int n_in,
                              void* d_out, int out_size) {
    const float* src       = (const float*)d_in[0];
    const float* pos_embed = (const float*)d_in[1];
    const int*   svi       = (const int*)  d_in[2];
    const float* in_proj_w = (const float*)d_in[4];
    const float* in_proj_b = (const float*)d_in[5];
    const float* out_w     = (const float*)d_in[6];
    const float* out_b     = (const float*)d_in[7];
    const float* lin1_w    = (const float*)d_in[8];
    const float* lin1_b    = (const float*)d_in[9];
    const float* lin2_w    = (const float*)d_in[10];
    const float* lin2_b    = (const float*)d_in[11];
    const float* ln1_g     = (const float*)d_in[12];
    const float* ln1_b     = (const float*)d_in[13];
    const float* ln2_g     = (const float*)d_in[14];
    const float* ln2_b     = (const float*)d_in[15];
    const float* enc_g     = (const float*)d_in[16];
    const float* enc_b     = (const float*)d_in[17];
    const float* blk_g     = (const float*)d_in[18];
    const float* blk_b     = (const float*)d_in[19];
    float* outp = (float*)d_out;

    float *X, *R;
    int *INV;
    __half *QKVh, *FOf, *Gf, *Qf, *AOf, *X1f, *Hf;
    __half *W0, *W1, *W2, *W3;
    cudaGetSymbolAddress((void**)&X,    g_X);
    cudaGetSymbolAddress((void**)&R,    g_R);    cudaGetSymbolAddress((void**)&INV, g_INV);
    cudaGetSymbolAddress((void**)&QKVh, g_QKVh); cudaGetSymbolAddress((void**)&FOf, g_FOf);
    cudaGetSymbolAddress((void**)&Gf,   g_Gf);   cudaGetSymbolAddress((void**)&Qf,  g_Qf);
    cudaGetSymbolAddress((void**)&AOf,  g_AOf);  cudaGetSymbolAddress((void**)&X1f, g_X1f);
    cudaGetSymbolAddress((void**)&Hf,   g_Hf);
    cudaGetSymbolAddress((void**)&W0,   g_W0);   cudaGetSymbolAddress((void**)&W1,  g_W1);
    cudaGetSymbolAddress((void**)&W2,   g_W2);   cudaGetSymbolAddress((void**)&W3,  g_W3);

    const int SMEM_GEMM = 49152;
    const int SMEM_OPLN = 65536;
    cudaFuncSetAttribute(gemm_mma<0>, cudaFuncAttributeMaxDynamicSharedMemorySize, SMEM_GEMM);
    cudaFuncSetAttribute(gemm_mma<1>, cudaFuncAttributeMaxDynamicSharedMemorySize, SMEM_GEMM);
    cudaFuncSetAttribute(gemm_oproj_ln, cudaFuncAttributeMaxDynamicSharedMemorySize, SMEM_OPLN);

    const size_t NC = (size_t)NV * CD;
    cudaMemcpyAsync(X, src, NC * sizeof(float), cudaMemcpyDeviceToDevice, 0);
    cudaMemcpyAsync(R, src, NC * sizeof(float), cudaMemcpyDeviceToDevice, 0);

    int totW = W0SZ + W1SZ + W2SZ + W3SZ;
    convw_k<<<(totW + 255) / 256, 256>>>(in_proj_w, out_w, lin1_w, lin2_w, W0, W1, W2, W3);
    invperm_k<<<(4 * NV + 255) / 256, 256>>>(svi, INV);

    dim3 lnGrid(NV / 8), lnBlk(32, 8);
    int gatherBlocks = (NV * (CD / 4) + 255) / 256;

    gather_k<<<gatherBlocks, 256>>>(X, pos_embed, svi, Gf, Qf);

    for (int blk = 0; blk < 4; blk++) {
        int shift = blk & 1;
        for (int i = 0; i < 2; i++) {
            int li = blk * 2 + i;
            const int* inds = svi + (size_t)(shift * 2 + i) * SETN * SETK;

            // QKV: cols [0,384) from Q-input, cols [384,576) from G
            gemm_mma<0><<<dim3(9, 576), 256, SMEM_GEMM>>>(
                Qf, Gf, 384,
                W0 + (size_t)li * 3 * CD * CD, in_proj_b + (size_t)li * 3 * CD,
                QKVh, nullptr, 3 * CD, CD);

            attn_k<<<dim3(SETN, HD), 128>>>(QKVh, AOf);

            // out-proj + scatter + add + LN1 (fused) -> X1f only
            gemm_oproj_ln<<<NV / 64, 256, SMEM_OPLN>>>(
                AOf, W1 + (size_t)li * CD * CD, out_b + (size_t)li * CD,
                inds, X, ln1_g + li * CD, ln1_b + li * CD, X1f);

            // ffn1 + gelu
            gemm_mma<1><<<dim3(6, 576), 256, SMEM_GEMM>>>(
                X1f, X1f, 1 << 30,
                W2 + (size_t)li * FF * CD, lin1_b + (size_t)li * FF,
                Hf, nullptr, FF, CD);

            // ffn2
            gemm_mma<0><<<dim3(3, 576), 256, SMEM_GEMM>>>(
                Hf, Hf, 1 << 30,
                W3 + (size_t)li * CD * FF, lin2_b + (size_t)li * CD,
                FOf, nullptr, CD, FF);

            bool blockEnd = (i == 1);
            bool last = (li == NLAYER - 1);
            const float* posn = nullptr; const int* invn = nullptr;
            __half *gf = nullptr, *qf = nullptr;
            if (!last) {
                int lnx = li + 1;
                int pn = ((lnx / 2) & 1) * 2 + (lnx & 1);
                posn = pos_embed + (size_t)(lnx & 1) * NC;
                invn = INV + (size_t)pn * NV;
                gf = Gf; qf = Qf;
            }
            fused_ln3_k<<<lnGrid, lnBlk>>>(
                X1f, FOf, X, blockEnd ? R : nullptr,
                ln2_g + li * CD, ln2_b + li * CD,
                enc_g + li * CD, enc_b + li * CD,
                blk_g + blk * CD, blk_b + blk * CD,
                last ? outp : X,
                (blockEnd && !last) ? R : nullptr,
                posn, invn, gf, qf);
        }
    }
}

// round 15
// speedup vs baseline: 1.0680x; 1.0253x over previous
#include <cuda_runtime.h>
#include <cuda_fp16.h>
#include <math.h>
#include <stdint.h>

#define NV   73728
#define CD   192
#define HD   8
#define DHD  24
#define FF   384
#define SETN 2048
#define SETK 36
#define NLAYER 8

// ================= helpers =================
__device__ __forceinline__ uint32_t smem_u32(const void* p) {
    uint32_t a;
    asm("{ .reg .u64 t; cvta.to.shared.u64 t, %1; cvt.u32.u64 %0, t; }" : "=r"(a) : "l"(p));
    return a;
}
__device__ __forceinline__ void cp_async16(uint32_t saddr, const void* gaddr) {
    asm volatile("cp.async.cg.shared.global [%0], [%1], 16;" :: "r"(saddr), "l"(gaddr) : "memory");
}
__device__ __forceinline__ void cp_commit() {
    asm volatile("cp.async.commit_group;" ::: "memory");
}
__device__ __forceinline__ void ldsm4(uint32_t* r, uint32_t a) {
    asm volatile("ldmatrix.sync.aligned.m8n8.x4.shared.b16 {%0,%1,%2,%3}, [%4];"
        : "=r"(r[0]), "=r"(r[1]), "=r"(r[2]), "=r"(r[3]) : "r"(a));
}
__device__ __forceinline__ void mma16816h(float* c, const uint32_t* a, uint32_t b0, uint32_t b1) {
    asm volatile("mma.sync.aligned.m16n8k16.row.col.f32.f16.f16.f32 "
        "{%0,%1,%2,%3}, {%4,%5,%6,%7}, {%8,%9}, {%0,%1,%2,%3};"
        : "+f"(c[0]), "+f"(c[1]), "+f"(c[2]), "+f"(c[3])
        : "r"(a[0]), "r"(a[1]), "r"(a[2]), "r"(a[3]), "r"(b0), "r"(b1));
}
__device__ __forceinline__ unsigned short h16(float x) {
    __half hb = __float2half_rn(x);
    return *reinterpret_cast<unsigned short*>(&hb);
}
__device__ __forceinline__ float2 h2f2u(uint32_t bits) {
    __half2 h = *reinterpret_cast<__half2*>(&bits);
    return __half22float2(h);
}
__device__ __forceinline__ float gelu_f(float x) {
    return 0.5f * x * (1.0f + erff(x * 0.70710678118654752440f));
}

// ================= scratch =================
__device__ int   g_INV[4*NV];
__device__ __half g_Xf [NV*CD];
__device__ __half g_Rf [NV*CD];
__device__ __half g_QKVh[NV*3*CD];
__device__ __half g_FOf[NV*CD];
__device__ __half g_Gf [NV*CD];
__device__ __half g_Qf [NV*CD];
__device__ __half g_AOf[NV*CD];
__device__ __half g_X1f[NV*CD];
__device__ __half g_Hf [NV*FF];
#define W0SZ (NLAYER*3*CD*CD)
#define W1SZ (NLAYER*CD*CD)
#define W2SZ (NLAYER*FF*CD)
#define W3SZ (NLAYER*CD*FF)
__device__ __half g_W0[W0SZ];
__device__ __half g_W1[W1SZ];
__device__ __half g_W2[W2SZ];
__device__ __half g_W3[W3SZ];

// ================= inverse permutations =================
__global__ void invperm_k(const int* __restrict__ svi, int* __restrict__ inv) {
    int i = blockIdx.x * 256 + threadIdx.x;
    if (i >= 4 * NV) return;
    int t = i / NV, p = i - t * NV;
    inv[t * NV + svi[i]] = p;
}

// ================= src -> fp16 X/R =================
__global__ void convsrc_k(const float* __restrict__ src,
                          __half* __restrict__ Xf, __half* __restrict__ Rf) {
    int e = blockIdx.x * 256 + threadIdx.x;
    if (e >= NV * (CD / 4)) return;
    float4 x = reinterpret_cast<const float4*>(src)[e];
    uint2 p = make_uint2((uint32_t)h16(x.x) | ((uint32_t)h16(x.y) << 16),
                         (uint32_t)h16(x.z) | ((uint32_t)h16(x.w) << 16));
    reinterpret_cast<uint2*>(Xf)[e] = p;
    reinterpret_cast<uint2*>(Rf)[e] = p;
}

// ================= weight conversion: single fp16 =================
__global__ void convw_k(const float* __restrict__ w0, const float* __restrict__ w1,
                        const float* __restrict__ w2, const float* __restrict__ w3,
                        __half* __restrict__ o0, __half* __restrict__ o1,
                        __half* __restrict__ o2, __half* __restrict__ o3) {
    int i = blockIdx.x * 256 + threadIdx.x;
    if (i < W0SZ) {
        o0[i] = __float2half_rn(w0[i]);
    } else if (i < W0SZ + W1SZ) {
        int j = i - W0SZ; o1[j] = __float2half_rn(w1[j]);
    } else if (i < W0SZ + W1SZ + W2SZ) {
        int j = i - W0SZ - W1SZ; o2[j] = __float2half_rn(w2[j]);
    } else if (i < W0SZ + W1SZ + W2SZ + W3SZ) {
        int j = i - W0SZ - W1SZ - W2SZ; o3[j] = __float2half_rn(w3[j]);
    }
}

// ================= layer-0 gather (reads fp32 src) -> fp16 =================
__global__ void gather_k(const float* __restrict__ X, const float* __restrict__ pos,
                         const int* __restrict__ inds,
                         __half* __restrict__ Gf, __half* __restrict__ Qf) {
    int e = blockIdx.x * 256 + threadIdx.x;
    const int C4 = CD / 4;
    if (e >= NV * C4) return;
    int row = e / C4, c4 = e - row * C4;
    int vox = inds[row];
    float4 x = reinterpret_cast<const float4*>(X)[(size_t)vox * C4 + c4];
    float4 p = reinterpret_cast<const float4*>(pos)[(size_t)vox * C4 + c4];
    uint2 g = make_uint2((uint32_t)h16(x.x) | ((uint32_t)h16(x.y) << 16),
                         (uint32_t)h16(x.z) | ((uint32_t)h16(x.w) << 16));
    uint2 q = make_uint2((uint32_t)h16(x.x + p.x) | ((uint32_t)h16(x.y + p.y) << 16),
                         (uint32_t)h16(x.z + p.z) | ((uint32_t)h16(x.w + p.w) << 16));
    reinterpret_cast<uint2*>(Gf)[(size_t)row * C4 + c4] = g;
    reinterpret_cast<uint2*>(Qf)[(size_t)row * C4 + c4] = q;
}

// ================= fp16 mma GEMM, 128x64 tile (R7 config) =================
template<int EPI>
__global__ void __launch_bounds__(256, 4)
gemm_mma(const __half* __restrict__ A0, const __half* __restrict__ A1, int a1ColStart,
         const __half* __restrict__ B, const float* __restrict__ bias,
         __half* __restrict__ outH, const int* __restrict__ scatter, int Nn, int K) {
    extern __shared__ char smem[];
    const int BUF = 24576;
    const int OF_A = 0, OF_B = 16384;
    uint32_t sb = smem_u32(smem);
    int tid = threadIdx.x, wid = tid >> 5, lane = tid & 31;
    int n0 = blockIdx.x * 64, m0 = blockIdx.y * 128;
    int wm = wid & 3, wn = wid >> 2;
    const __half* __restrict__ A = (n0 >= a1ColStart) ? A1 : A0;

    int arow[4], acol[4]; uint32_t asf[4];
    int brow[2], bcol[2]; uint32_t bsf[2];
    #pragma unroll
    for (int i = 0; i < 4; i++) {
        int c = tid + (i << 8); int r = c >> 3, c8 = c & 7;
        arow[i] = r; acol[i] = c8 * 8;
        asf[i] = (uint32_t)(r * 128 + ((c8 * 16) ^ ((r & 7) << 4)));
    }
    #pragma unroll
    for (int i = 0; i < 2; i++) {
        int c = tid + (i << 8); int r = c >> 3, c8 = c & 7;
        brow[i] = r; bcol[i] = c8 * 8;
        bsf[i] = (uint32_t)(r * 128 + ((c8 * 16) ^ ((r & 7) << 4)));
    }

    int nstages = K >> 6;
    {
        #pragma unroll
        for (int i = 0; i < 4; i++)
            cp_async16(sb + OF_A + asf[i], A + (size_t)(m0 + arow[i]) * K + acol[i]);
        #pragma unroll
        for (int i = 0; i < 2; i++)
            cp_async16(sb + OF_B + bsf[i], B + (size_t)(n0 + brow[i]) * K + bcol[i]);
        cp_commit();
    }

    float acc[2][4][4] = {};
    int q = lane >> 3, j = lane & 7;

    for (int s = 0; s < nstages; s++) {
        asm volatile("cp.async.wait_group 0;" ::: "memory");
        __syncthreads();
        if (s + 1 < nstages) {
            uint32_t base = sb + ((s + 1) & 1) * BUF;
            int koff = (s + 1) * 64;
            #pragma unroll
            for (int i = 0; i < 4; i++)
                cp_async16(base + OF_A + asf[i], A + (size_t)(m0 + arow[i]) * K + koff + acol[i]);
            #pragma unroll
            for (int i = 0; i < 2; i++)
                cp_async16(base + OF_B + bsf[i], B + (size_t)(n0 + brow[i]) * K + koff + bcol[i]);
            cp_commit();
        }
        uint32_t base = sb + (s & 1) * BUF;

        #pragma unroll
        for (int kc = 0; kc < 4; kc++) {
            uint32_t af[2][4], bf[2][4];
            #pragma unroll
            for (int mt = 0; mt < 2; mt++) {
                int row = wm * 32 + mt * 16 + (q & 1) * 8 + j;
                int cb = kc * 32 + (q >> 1) * 16;
                uint32_t so = (uint32_t)(row * 128 + (cb ^ ((row & 7) << 4)));
                ldsm4(af[mt], base + OF_A + so);
            }
            #pragma unroll
            for (int np = 0; np < 2; np++) {
                int row = wn * 32 + np * 16 + (q >> 1) * 8 + j;
                int cb = kc * 32 + (q & 1) * 16;
                uint32_t so = (uint32_t)(row * 128 + (cb ^ ((row & 7) << 4)));
                ldsm4(bf[np], base + OF_B + so);
            }
            #pragma unroll
            for (int mt = 0; mt < 2; mt++) {
                #pragma unroll
                for (int nt = 0; nt < 4; nt++) {
                    uint32_t b0 = bf[nt >> 1][(nt & 1) * 2], b1 = bf[nt >> 1][(nt & 1) * 2 + 1];
                    mma16816h(acc[mt][nt], af[mt], b0, b1);
                }
            }
        }
    }

    int r4 = lane >> 2, cg = (lane & 3) * 2;
    #pragma unroll
    for (int mt = 0; mt < 2; mt++) {
        int mrow0 = m0 + wm * 32 + mt * 16 + r4;
        int mrow1 = mrow0 + 8;
        int o0 = scatter ? scatter[mrow0] : mrow0;
        int o1 = scatter ? scatter[mrow1] : mrow1;
        #pragma unroll
        for (int nt = 0; nt < 4; nt++) {
            int col = n0 + wn * 32 + nt * 8 + cg;
            float b0 = bias[col], b1 = bias[col + 1];
            float v00 = acc[mt][nt][0] + b0, v01 = acc[mt][nt][1] + b1;
            float v10 = acc[mt][nt][2] + b0, v11 = acc[mt][nt][3] + b1;
            if (EPI == 1) { v00 = gelu_f(v00); v01 = gelu_f(v01); v10 = gelu_f(v10); v11 = gelu_f(v11); }
            *reinterpret_cast<uint32_t*>(outH + (size_t)o0 * Nn + col) =
                (uint32_t)h16(v00) | ((uint32_t)h16(v01) << 16);
            *reinterpret_cast<uint32_t*>(outH + (size_t)o1 * Nn + col) =
                (uint32_t)h16(v10) | ((uint32_t)h16(v11) << 16);
        }
    }
}

// ========= fused out-proj GEMM (64x192 tile) + add + LayerNorm epilogue =========
// X identity stream now fp16. Writes LN result only as fp16 X1f.
__global__ void __launch_bounds__(256, 2)
gemm_oproj_ln(const __half* __restrict__ A, const __half* __restrict__ B,
              const float* __restrict__ bias, const int* __restrict__ inds,
              const __half* __restrict__ Xf,
              const float* __restrict__ lng, const float* __restrict__ lnb,
              __half* __restrict__ X1f) {
    extern __shared__ char smem[];
    const int BUF = 32768;
    const int OF_A = 0, OF_B = 8192;
    uint32_t sb = smem_u32(smem);
    int tid = threadIdx.x, wid = tid >> 5, lane = tid & 31;
    int m0 = blockIdx.x * 64;
    int gq = wid >> 1, wn = wid & 1;

    const int K = CD;
    const int nstages = 3;

    {
        #pragma unroll
        for (int i = 0; i < 2; i++) {
            int c = tid + (i << 8); int r = c >> 3, c8 = c & 7;
            uint32_t sf = (uint32_t)(r * 128 + ((c8 * 16) ^ ((r & 7) << 4)));
            cp_async16(sb + OF_A + sf, A + (size_t)(m0 + r) * K + c8 * 8);
        }
        #pragma unroll
        for (int i = 0; i < 6; i++) {
            int c = tid + (i << 8); int r = c >> 3, c8 = c & 7;
            uint32_t sf = (uint32_t)(r * 128 + ((c8 * 16) ^ ((r & 7) << 4)));
            cp_async16(sb + OF_B + sf, B + (size_t)r * K + c8 * 8);
        }
        cp_commit();
    }

    float acc[12][4] = {};
    int q = lane >> 3, j = lane & 7;

    for (int s = 0; s < nstages; s++) {
        asm volatile("cp.async.wait_group 0;" ::: "memory");
        __syncthreads();
        if (s + 1 < nstages) {
            uint32_t base = sb + ((s + 1) & 1) * BUF;
            int koff = (s + 1) * 64;
            #pragma unroll
            for (int i = 0; i < 2; i++) {
                int c = tid + (i << 8); int r = c >> 3, c8 = c & 7;
                uint32_t sf = (uint32_t)(r * 128 + ((c8 * 16) ^ ((r & 7) << 4)));
                cp_async16(base + OF_A + sf, A + (size_t)(m0 + r) * K + koff + c8 * 8);
            }
            #pragma unroll
            for (int i = 0; i < 6; i++) {
                int c = tid + (i << 8); int r = c >> 3, c8 = c & 7;
                uint32_t sf = (uint32_t)(r * 128 + ((c8 * 16) ^ ((r & 7) << 4)));
                cp_async16(base + OF_B + sf, B + (size_t)r * K + koff + c8 * 8);
            }
            cp_commit();
        }
        uint32_t base = sb + (s & 1) * BUF;

        #pragma unroll
        for (int kc = 0; kc < 4; kc++) {
            uint32_t af[4];
            {
                int row = gq * 16 + (q & 1) * 8 + j;
                int cb = kc * 32 + (q >> 1) * 16;
                uint32_t so = (uint32_t)(row * 128 + (cb ^ ((row & 7) << 4)));
                ldsm4(af, base + OF_A + so);
            }
            #pragma unroll
            for (int np = 0; np < 6; np++) {
                uint32_t bf[4];
                int row = wn * 96 + np * 16 + (q >> 1) * 8 + j;
                int cb = kc * 32 + (q & 1) * 16;
                uint32_t so = (uint32_t)(row * 128 + (cb ^ ((row & 7) << 4)));
                ldsm4(bf, base + OF_B + so);
                mma16816h(acc[np * 2 + 0], af, bf[0], bf[1]);
                mma16816h(acc[np * 2 + 1], af, bf[2], bf[3]);
            }
        }
    }

    int r4 = lane >> 2, cg = (lane & 3) * 2;
    int lrowA = gq * 16 + r4, lrowB = lrowA + 8;
    int oA = inds[m0 + lrowA], oB = inds[m0 + lrowB];

    float sA = 0.f, s2A = 0.f, sB = 0.f, s2B = 0.f;
    #pragma unroll
    for (int nt = 0; nt < 12; nt++) {
        int col = wn * 96 + nt * 8 + cg;
        float b0 = bias[col], b1 = bias[col + 1];
        float2 xA = h2f2u(*reinterpret_cast<const uint32_t*>(Xf + (size_t)oA * CD + col));
        float2 xB = h2f2u(*reinterpret_cast<const uint32_t*>(Xf + (size_t)oB * CD + col));
        float v0 = acc[nt][0] + b0 + xA.x, v1 = acc[nt][1] + b1 + xA.y;
        float v2 = acc[nt][2] + b0 + xB.x, v3 = acc[nt][3] + b1 + xB.y;
        acc[nt][0] = v0; acc[nt][1] = v1; acc[nt][2] = v2; acc[nt][3] = v3;
        sA += v0 + v1; s2A += v0 * v0 + v1 * v1;
        sB += v2 + v3; s2B += v2 * v2 + v3 * v3;
    }
    #pragma unroll
    for (int o = 1; o <= 2; o <<= 1) {
        sA  += __shfl_xor_sync(0xffffffffu, sA,  o);
        s2A += __shfl_xor_sync(0xffffffffu, s2A, o);
        sB  += __shfl_xor_sync(0xffffffffu, sB,  o);
        s2B += __shfl_xor_sync(0xffffffffu, s2B, o);
    }
    float* red = reinterpret_cast<float*>(smem);
    __syncthreads();
    if ((lane & 3) == 0) {
        red[(wn * 64 + lrowA) * 2 + 0] = sA;
        red[(wn * 64 + lrowA) * 2 + 1] = s2A;
        red[(wn * 64 + lrowB) * 2 + 0] = sB;
        red[(wn * 64 + lrowB) * 2 + 1] = s2B;
    }
    __syncthreads();
    float tsA  = red[lrowA * 2 + 0] + red[(64 + lrowA) * 2 + 0];
    float ts2A = red[lrowA * 2 + 1] + red[(64 + lrowA) * 2 + 1];
    float tsB  = red[lrowB * 2 + 0] + red[(64 + lrowB) * 2 + 0];
    float ts2B = red[lrowB * 2 + 1] + red[(64 + lrowB) * 2 + 1];
    float mA = tsA * (1.0f / CD), vA = ts2A * (1.0f / CD) - mA * mA;
    float mB = tsB * (1.0f / CD), vB = ts2B * (1.0f / CD) - mB * mB;
    float rA = rsqrtf(vA + 1e-5f), rB = rsqrtf(vB + 1e-5f);

    #pragma unroll
    for (int nt = 0; nt < 12; nt++) {
        int col = wn * 96 + nt * 8 + cg;
        float g0 = lng[col], g1 = lng[col + 1];
        float bb0 = lnb[col], bb1 = lnb[col + 1];
        float y0 = (acc[nt][0] - mA) * rA * g0 + bb0;
        float y1 = (acc[nt][1] - mA) * rA * g1 + bb1;
        float y2 = (acc[nt][2] - mB) * rB * g0 + bb0;
        float y3 = (acc[nt][3] - mB) * rB * g1 + bb1;
        *reinterpret_cast<uint32_t*>(X1f + (size_t)oA * CD + col) =
            (uint32_t)h16(y0) | ((uint32_t)h16(y1) << 16);
        *reinterpret_cast<uint32_t*>(X1f + (size_t)oB * CD + col) =
            (uint32_t)h16(y2) | ((uint32_t)h16(y3) << 16);
    }
}

// ===== per (set, head) attention — R12 version (4r x 1l broadcast QK) =====
#define DP 28
__global__ void __launch_bounds__(128)
attn_k(const __half* __restrict__ QKV, __half* __restrict__ AOf) {
    int s = blockIdx.x, h = blockIdx.y;
    __shared__ float q[SETK][DP], k[SETK][DP], v[SETK][DP];
    __shared__ float sc[SETK][SETK];
    int tid = threadIdx.x;
    const __half* base = QKV + (size_t)s * SETK * (3 * CD) + h * DHD;
    for (int t = tid; t < SETK * 6; t += 128) {
        int r = t / 6, c4 = t - r * 6;
        const __half* rp = base + r * (3 * CD) + c4 * 4;
        const __half2* qp = reinterpret_cast<const __half2*>(rp);
        const __half2* kp = reinterpret_cast<const __half2*>(rp + CD);
        const __half2* vp = reinterpret_cast<const __half2*>(rp + 2 * CD);
        float2 a0 = __half22float2(qp[0]), a1 = __half22float2(qp[1]);
        q[r][c4*4+0] = a0.x; q[r][c4*4+1] = a0.y; q[r][c4*4+2] = a1.x; q[r][c4*4+3] = a1.y;
        float2 b0 = __half22float2(kp[0]), b1 = __half22float2(kp[1]);
        k[r][c4*4+0] = b0.x; k[r][c4*4+1] = b0.y; k[r][c4*4+2] = b1.x; k[r][c4*4+3] = b1.y;
        float2 c0 = __half22float2(vp[0]), c1 = __half22float2(vp[1]);
        v[r][c4*4+0] = c0.x; v[r][c4*4+1] = c0.y; v[r][c4*4+2] = c1.x; v[r][c4*4+3] = c1.y;
    }
    __syncthreads();
    const float scale = 0.20412414523193150818f;
    for (int u = tid; u < 9 * SETK; u += 128) {
        int rq = u / SETK, l = u - rq * SETK;
        int r0 = rq * 4;
        float a0 = 0.f, a1 = 0.f, a2 = 0.f, a3 = 0.f;
        #pragma unroll
        for (int c4 = 0; c4 < 6; c4++) {
            float4 b  = *reinterpret_cast<const float4*>(&k[l][c4 * 4]);
            float4 q0 = *reinterpret_cast<const float4*>(&q[r0 + 0][c4 * 4]);
            float4 q1 = *reinterpret_cast<const float4*>(&q[r0 + 1][c4 * 4]);
            float4 q2 = *reinterpret_cast<const float4*>(&q[r0 + 2][c4 * 4]);
            float4 q3 = *reinterpret_cast<const float4*>(&q[r0 + 3][c4 * 4]);
            a0 = fmaf(q0.x, b.x, a0); a0 = fmaf(q0.y, b.y, a0);
            a0 = fmaf(q0.z, b.z, a0); a0 = fmaf(q0.w, b.w, a0);
            a1 = fmaf(q1.x, b.x, a1); a1 = fmaf(q1.y, b.y, a1);
            a1 = fmaf(q1.z, b.z, a1); a1 = fmaf(q1.w, b.w, a1);
            a2 = fmaf(q2.x, b.x, a2); a2 = fmaf(q2.y, b.y, a2);
            a2 = fmaf(q2.z, b.z, a2); a2 = fmaf(q2.w, b.w, a2);
            a3 = fmaf(q3.x, b.x, a3); a3 = fmaf(q3.y, b.y, a3);
            a3 = fmaf(q3.z, b.z, a3); a3 = fmaf(q3.w, b.w, a3);
        }
        sc[r0 + 0][l] = a0 * scale;
        sc[r0 + 1][l] = a1 * scale;
        sc[r0 + 2][l] = a2 * scale;
        sc[r0 + 3][l] = a3 * scale;
    }
    __syncthreads();
    if (tid < SETK) {
        int r = tid;
        float4 rowv[9];
        #pragma unroll
        for (int i = 0; i < 9; i++) rowv[i] = *reinterpret_cast<const float4*>(&sc[r][i * 4]);
        float mx = -1e30f;
        #pragma unroll
        for (int i = 0; i < 9; i++)
            mx = fmaxf(mx, fmaxf(fmaxf(rowv[i].x, rowv[i].y), fmaxf(rowv[i].z, rowv[i].w)));
        float sum = 0.f;
        #pragma unroll
        for (int i = 0; i < 9; i++) {
            rowv[i].x = expf(rowv[i].x - mx); rowv[i].y = expf(rowv[i].y - mx);
            rowv[i].z = expf(rowv[i].z - mx); rowv[i].w = expf(rowv[i].w - mx);
            sum += rowv[i].x + rowv[i].y + rowv[i].z + rowv[i].w;
        }
        float inv = 1.0f / sum;
        #pragma unroll
        for (int i = 0; i < 9; i++) {
            rowv[i].x *= inv; rowv[i].y *= inv; rowv[i].z *= inv; rowv[i].w *= inv;
            *reinterpret_cast<float4*>(&sc[r][i * 4]) = rowv[i];
        }
    }
    __syncthreads();
    for (int u = tid; u < SETK * 6; u += 128) {
        int r = u / 6, c4 = u - r * 6;
        float4 acc = make_float4(0.f, 0.f, 0.f, 0.f);
        #pragma unroll 4
        for (int l = 0; l < SETK; l++) {
            float w = sc[r][l];
            float4 vv = *reinterpret_cast<const float4*>(&v[l][c4 * 4]);
            acc.x = fmaf(w, vv.x, acc.x); acc.y = fmaf(w, vv.y, acc.y);
            acc.z = fmaf(w, vv.z, acc.z); acc.w = fmaf(w, vv.w, acc.w);
        }
        size_t ob = (size_t)(s * SETK + r) * CD + h * DHD + c4 * 4;
        *reinterpret_cast<uint2*>(AOf + ob) =
            make_uint2((uint32_t)h16(acc.x) | ((uint32_t)h16(acc.y) << 16),
                       (uint32_t)h16(acc.z) | ((uint32_t)h16(acc.w) << 16));
    }
}

// ================= warp LayerNorm (lane -> 6 consecutive cols) =================
__device__ __forceinline__ void warp_ln6c(float (&x)[6], const float* __restrict__ g,
                                          const float* __restrict__ b, int cbase, float (&y)[6]) {
    float s = 0.f, s2 = 0.f;
    #pragma unroll
    for (int j = 0; j < 6; j++) { s += x[j]; s2 += x[j] * x[j]; }
    #pragma unroll
    for (int o = 16; o > 0; o >>= 1) {
        s  += __shfl_xor_sync(0xffffffffu, s, o);
        s2 += __shfl_xor_sync(0xffffffffu, s2, o);
    }
    float mean = s * (1.0f / CD);
    float var  = s2 * (1.0f / CD) - mean * mean;
    float r = rsqrtf(var + 1e-5f);
    #pragma unroll
    for (int j = 0; j < 6; j++)
        y[j] = (x[j] - mean) * r * g[cbase + j] + b[cbase + j];
}
__device__ __forceinline__ void load6(const float* p, float (&x)[6]) {
    float2 a = *reinterpret_cast<const float2*>(p);
    float2 b = *reinterpret_cast<const float2*>(p + 2);
    float2 c = *reinterpret_cast<const float2*>(p + 4);
    x[0]=a.x; x[1]=a.y; x[2]=b.x; x[3]=b.y; x[4]=c.x; x[5]=c.y;
}
__device__ __forceinline__ void load6h(const __half* p, float (&x)[6]) {
    const __half2* hp = reinterpret_cast<const __half2*>(p);
    float2 a = __half22float2(hp[0]);
    float2 b = __half22float2(hp[1]);
    float2 c = __half22float2(hp[2]);
    x[0]=a.x; x[1]=a.y; x[2]=b.x; x[3]=b.y; x[4]=c.x; x[5]=c.y;
}
__device__ __forceinline__ void store6(float* p, const float (&y)[6]) {
    *reinterpret_cast<float2*>(p)     = make_float2(y[0], y[1]);
    *reinterpret_cast<float2*>(p + 2) = make_float2(y[2], y[3]);
    *reinterpret_cast<float2*>(p + 4) = make_float2(y[4], y[5]);
}
__device__ __forceinline__ void store6_h(__half* ph, const float (&y)[6]) {
    *reinterpret_cast<uint32_t*>(ph)     = (uint32_t)h16(y[0]) | ((uint32_t)h16(y[1]) << 16);
    *reinterpret_cast<uint32_t*>(ph + 2) = (uint32_t)h16(y[2]) | ((uint32_t)h16(y[3]) << 16);
    *reinterpret_cast<uint32_t*>(ph + 4) = (uint32_t)h16(y[4]) | ((uint32_t)h16(y[5]) << 16);
}

// LN chain: all activation streams fp16; out = fp32 (last layer) or fp16 Xf
__global__ void __launch_bounds__(256)
fused_ln3_k(const __half* __restrict__ X1f, const __half* __restrict__ FOf,
            const __half* __restrict__ IDf, const __half* __restrict__ RESf,
            const float* __restrict__ g2, const float* __restrict__ b2,
            const float* __restrict__ ge, const float* __restrict__ be,
            const float* __restrict__ gb, const float* __restrict__ bb,
            float* __restrict__ outF, __half* __restrict__ outXf,
            __half* __restrict__ Rdst,
            const float* __restrict__ posn, const int* __restrict__ invn,
            __half* __restrict__ Gf, __half* __restrict__ Qf) {
    int row = blockIdx.x * blockDim.y + threadIdx.y;
    int cbase = threadIdx.x * 6;
    size_t off = (size_t)row * CD + cbase;
    float x[6], t[6], y[6];
    load6h(X1f + off, x); load6h(FOf + off, t);
    #pragma unroll
    for (int j = 0; j < 6; j++) x[j] += t[j];
    warp_ln6c(x, g2, b2, cbase, y);
    load6h(IDf + off, t);
    #pragma unroll
    for (int j = 0; j < 6; j++) x[j] = y[j] + t[j];
    warp_ln6c(x, ge, be, cbase, y);
    if (RESf) {
        load6h(RESf + off, t);
        #pragma unroll
        for (int j = 0; j < 6; j++) x[j] = y[j] + t[j];
        warp_ln6c(x, gb, bb, cbase, y);
    }
    if (outF) store6(outF + off, y);
    if (outXf) store6_h(outXf + off, y);
    if (Rdst) store6_h(Rdst + off, y);
    if (Gf) {
        int p = invn[row];
        size_t soff = (size_t)p * CD + cbase;
        store6_h(Gf + soff, y);
        float q[6];
        load6(posn + off, t);
        #pragma unroll
        for (int j = 0; j < 6; j++) q[j] = y[j] + t[j];
        store6_h(Qf + soff, q);
    }
}

// ================= host =================
extern "C" void kernel_launch(void* const* d_in, const int* in_sizes, int n_in,
                              void* d_out, int out_size) {
    const float* src       = (const float*)d_in[0];
    const float* pos_embed = (const float*)d_in[1];
    const int*   svi       = (const int*)  d_in[2];
    const float* in_proj_w = (const float*)d_in[4];
    const float* in_proj_b = (const float*)d_in[5];
    const float* out_w     = (const float*)d_in[6];
    const float* out_b     = (const float*)d_in[7];
    const float* lin1_w    = (const float*)d_in[8];
    const float* lin1_b    = (const float*)d_in[9];
    const float* lin2_w    = (const float*)d_in[10];
    const float* lin2_b    = (const float*)d_in[11];
    const float* ln1_g     = (const float*)d_in[12];
    const float* ln1_b     = (const float*)d_in[13];
    const float* ln2_g     = (const float*)d_in[14];
    const float* ln2_b     = (const float*)d_in[15];
    const float* enc_g     = (const float*)d_in[16];
    const float* enc_b     = (const float*)d_in[17];
    const float* blk_g     = (const float*)d_in[18];
    const float* blk_b     = (const float*)d_in[19];
    float* outp = (float*)d_out;

    int *INV;
    __half *Xf, *Rf, *QKVh, *FOf, *Gf, *Qf, *AOf, *X1f, *Hf;
    __half *W0, *W1, *W2, *W3;
    cudaGetSymbolAddress((void**)&Xf,   g_Xf);   cudaGetSymbolAddress((void**)&Rf,  g_Rf);
    cudaGetSymbolAddress((void**)&INV,  g_INV);
    cudaGetSymbolAddress((void**)&QKVh, g_QKVh); cudaGetSymbolAddress((void**)&FOf, g_FOf);
    cudaGetSymbolAddress((void**)&Gf,   g_Gf);   cudaGetSymbolAddress((void**)&Qf,  g_Qf);
    cudaGetSymbolAddress((void**)&AOf,  g_AOf);  cudaGetSymbolAddress((void**)&X1f, g_X1f);
    cudaGetSymbolAddress((void**)&Hf,   g_Hf);
    cudaGetSymbolAddress((void**)&W0,   g_W0);   cudaGetSymbolAddress((void**)&W1,  g_W1);
    cudaGetSymbolAddress((void**)&W2,   g_W2);   cudaGetSymbolAddress((void**)&W3,  g_W3);

    const int SMEM_GEMM = 49152;
    const int SMEM_OPLN = 65536;
    cudaFuncSetAttribute(gemm_mma<0>, cudaFuncAttributeMaxDynamicSharedMemorySize, SMEM_GEMM);
    cudaFuncSetAttribute(gemm_mma<1>, cudaFuncAttributeMaxDynamicSharedMemorySize, SMEM_GEMM);
    cudaFuncSetAttribute(gemm_oproj_ln, cudaFuncAttributeMaxDynamicSharedMemorySize, SMEM_OPLN);

    const size_t NC = (size_t)NV * CD;

    int totW = W0SZ + W1SZ + W2SZ + W3SZ;
    convw_k<<<(totW + 255) / 256, 256>>>(in_proj_w, out_w, lin1_w, lin2_w, W0, W1, W2, W3);
    invperm_k<<<(4 * NV + 255) / 256, 256>>>(svi, INV);
    int cvBlocks = (NV * (CD / 4) + 255) / 256;
    convsrc_k<<<cvBlocks, 256>>>(src, Xf, Rf);

    dim3 lnGrid(NV / 8), lnBlk(32, 8);
    gather_k<<<cvBlocks, 256>>>(src, pos_embed, svi, Gf, Qf);

    for (int blk = 0; blk < 4; blk++) {
        int shift = blk & 1;
        for (int i = 0; i < 2; i++) {
            int li = blk * 2 + i;
            const int* inds = svi + (size_t)(shift * 2 + i) * SETN * SETK;

            // QKV: cols [0,384) from Q-input, cols [384,576) from G
            gemm_mma<0><<<dim3(9, 576), 256, SMEM_GEMM>>>(
                Qf, Gf, 384,
                W0 + (size_t)li * 3 * CD * CD, in_proj_b + (size_t)li * 3 * CD,
                QKVh, nullptr, 3 * CD, CD);

            attn_k<<<dim3(SETN, HD), 128>>>(QKVh, AOf);

            // out-proj + scatter + add + LN1 (fused) -> X1f only
            gemm_oproj_ln<<<NV / 64, 256, SMEM_OPLN>>>(
                AOf, W1 + (size_t)li * CD * CD, out_b + (size_t)li * CD,
                inds, Xf, ln1_g + li * CD, ln1_b + li * CD, X1f);

            // ffn1 + gelu
            gemm_mma<1><<<dim3(6, 576), 256, SMEM_GEMM>>>(
                X1f, X1f, 1 << 30,
                W2 + (size_t)li * FF * CD, lin1_b + (size_t)li * FF,
                Hf, nullptr, FF, CD);

            // ffn2
            gemm_mma<0><<<dim3(3, 576), 256, SMEM_GEMM>>>(
                Hf, Hf, 1 << 30,
                W3 + (size_t)li * CD * FF, lin2_b + (size_t)li * CD,
                FOf, nullptr, CD, FF);

            bool blockEnd = (i == 1);
            bool last = (li == NLAYER - 1);
            const float* posn = nullptr; const int* invn = nullptr;
            __half *gf = nullptr, *qf = nullptr;
            if (!last) {
                int lnx = li + 1;
                int pn = ((lnx / 2) & 1) * 2 + (lnx & 1);
                posn = pos_embed + (size_t)(lnx & 1) * NC;
                invn = INV + (size_t)pn * NV;
                gf = Gf; qf = Qf;
            }
            fused_ln3_k<<<lnGrid, lnBlk>>>(
                X1f, FOf, Xf, blockEnd ? Rf : nullptr,
                ln2_g + li * CD, ln2_b + li * CD,
                enc_g + li * CD, enc_b + li * CD,
                blk_g + blk * CD, blk_b + blk * CD,
                last ? outp : nullptr, last ? nullptr : Xf,
                (blockEnd && !last) ? Rf : nullptr,
                posn, invn, gf, qf);
        }
    }
}

// round 16
// speedup vs baseline: 1.0834x; 1.0145x over previous
#include <cuda_runtime.h>
#include <cuda_fp16.h>
#include <math.h>
#include <stdint.h>

#define NV   73728
#define CD   192
#define HD   8
#define DHD  24
#define FF   384
#define SETN 2048
#define SETK 36
#define NLAYER 8

// ================= helpers =================
__device__ __forceinline__ uint32_t smem_u32(const void* p) {
    uint32_t a;
    asm("{ .reg .u64 t; cvta.to.shared.u64 t, %1; cvt.u32.u64 %0, t; }" : "=r"(a) : "l"(p));
    return a;
}
__device__ __forceinline__ void cp_async16(uint32_t saddr, const void* gaddr) {
    asm volatile("cp.async.cg.shared.global [%0], [%1], 16;" :: "r"(saddr), "l"(gaddr) : "memory");
}
__device__ __forceinline__ void cp_commit() {
    asm volatile("cp.async.commit_group;" ::: "memory");
}
__device__ __forceinline__ void ldsm4(uint32_t* r, uint32_t a) {
    asm volatile("ldmatrix.sync.aligned.m8n8.x4.shared.b16 {%0,%1,%2,%3}, [%4];"
        : "=r"(r[0]), "=r"(r[1]), "=r"(r[2]), "=r"(r[3]) : "r"(a));
}
__device__ __forceinline__ void mma16816h(float* c, const uint32_t* a, uint32_t b0, uint32_t b1) {
    asm volatile("mma.sync.aligned.m16n8k16.row.col.f32.f16.f16.f32 "
        "{%0,%1,%2,%3}, {%4,%5,%6,%7}, {%8,%9}, {%0,%1,%2,%3};"
        : "+f"(c[0]), "+f"(c[1]), "+f"(c[2]), "+f"(c[3])
        : "r"(a[0]), "r"(a[1]), "r"(a[2]), "r"(a[3]), "r"(b0), "r"(b1));
}
__device__ __forceinline__ unsigned short h16(float x) {
    __half hb = __float2half_rn(x);
    return *reinterpret_cast<unsigned short*>(&hb);
}
__device__ __forceinline__ float2 h2f2u(uint32_t bits) {
    __half2 h = *reinterpret_cast<__half2*>(&bits);
    return __half22float2(h);
}
__device__ __forceinline__ float gelu_f(float x) {
    return 0.5f * x * (1.0f + erff(x * 0.70710678118654752440f));
}

// ================= scratch =================
__device__ int   g_INV[4*NV];
__device__ __half g_Xf [NV*CD];
__device__ __half g_Rf [NV*CD];
__device__ __half g_QKVh[NV*3*CD];
__device__ __half g_FOf[NV*CD];
__device__ __half g_Gf [NV*CD];
__device__ __half g_Qf [NV*CD];
__device__ __half g_AOf[NV*CD];
__device__ __half g_X1f[NV*CD];
__device__ __half g_Hf [NV*FF];
#define W0SZ (NLAYER*3*CD*CD)
#define W1SZ (NLAYER*CD*CD)
#define W2SZ (NLAYER*FF*CD)
#define W3SZ (NLAYER*CD*FF)
__device__ __half g_W0[W0SZ];
__device__ __half g_W1[W1SZ];
__device__ __half g_W2[W2SZ];
__device__ __half g_W3[W3SZ];

// ================= inverse permutations =================
__global__ void invperm_k(const int* __restrict__ svi, int* __restrict__ inv) {
    int i = blockIdx.x * 256 + threadIdx.x;
    if (i >= 4 * NV) return;
    int t = i / NV, p = i - t * NV;
    inv[t * NV + svi[i]] = p;
}

// ================= src -> fp16 X/R =================
__global__ void convsrc_k(const float* __restrict__ src,
                          __half* __restrict__ Xf, __half* __restrict__ Rf) {
    int e = blockIdx.x * 256 + threadIdx.x;
    if (e >= NV * (CD / 4)) return;
    float4 x = reinterpret_cast<const float4*>(src)[e];
    uint2 p = make_uint2((uint32_t)h16(x.x) | ((uint32_t)h16(x.y) << 16),
                         (uint32_t)h16(x.z) | ((uint32_t)h16(x.w) << 16));
    reinterpret_cast<uint2*>(Xf)[e] = p;
    reinterpret_cast<uint2*>(Rf)[e] = p;
}

// ================= weight conversion: single fp16 =================
__global__ void convw_k(const float* __restrict__ w0, const float* __restrict__ w1,
                        const float* __restrict__ w2, const float* __restrict__ w3,
                        __half* __restrict__ o0, __half* __restrict__ o1,
                        __half* __restrict__ o2, __half* __restrict__ o3) {
    int i = blockIdx.x * 256 + threadIdx.x;
    if (i < W0SZ) {
        o0[i] = __float2half_rn(w0[i]);
    } else if (i < W0SZ + W1SZ) {
        int j = i - W0SZ; o1[j] = __float2half_rn(w1[j]);
    } else if (i < W0SZ + W1SZ + W2SZ) {
        int j = i - W0SZ - W1SZ; o2[j] = __float2half_rn(w2[j]);
    } else if (i < W0SZ + W1SZ + W2SZ + W3SZ) {
        int j = i - W0SZ - W1SZ - W2SZ; o3[j] = __float2half_rn(w3[j]);
    }
}

// ================= layer-0 gather (reads fp32 src) -> fp16 =================
__global__ void gather_k(const float* __restrict__ X, const float* __restrict__ pos,
                         const int* __restrict__ inds,
                         __half* __restrict__ Gf, __half* __restrict__ Qf) {
    int e = blockIdx.x * 256 + threadIdx.x;
    const int C4 = CD / 4;
    if (e >= NV * C4) return;
    int row = e / C4, c4 = e - row * C4;
    int vox = inds[row];
    float4 x = reinterpret_cast<const float4*>(X)[(size_t)vox * C4 + c4];
    float4 p = reinterpret_cast<const float4*>(pos)[(size_t)vox * C4 + c4];
    uint2 g = make_uint2((uint32_t)h16(x.x) | ((uint32_t)h16(x.y) << 16),
                         (uint32_t)h16(x.z) | ((uint32_t)h16(x.w) << 16));
    uint2 q = make_uint2((uint32_t)h16(x.x + p.x) | ((uint32_t)h16(x.y + p.y) << 16),
                         (uint32_t)h16(x.z + p.z) | ((uint32_t)h16(x.w + p.w) << 16));
    reinterpret_cast<uint2*>(Gf)[(size_t)row * C4 + c4] = g;
    reinterpret_cast<uint2*>(Qf)[(size_t)row * C4 + c4] = q;
}

// ================= fp16 mma GEMM, 256x64 tile (R8 config, fp16 out) =================
template<int EPI>
__global__ void __launch_bounds__(256, 2)
gemm_mma(const __half* __restrict__ A0, const __half* __restrict__ A1, int a1ColStart,
         const __half* __restrict__ B, const float* __restrict__ bias,
         __half* __restrict__ outH, const int* __restrict__ scatter, int Nn, int K) {
    extern __shared__ char smem[];
    const int BUF = 40960;
    const int OF_A = 0, OF_B = 32768;
    uint32_t sb = smem_u32(smem);
    int tid = threadIdx.x, wid = tid >> 5, lane = tid & 31;
    int n0 = blockIdx.x * 64, m0 = blockIdx.y * 256;
    int wm = wid;
    const __half* __restrict__ A = (n0 >= a1ColStart) ? A1 : A0;

    int nstages = K >> 6;
    {
        #pragma unroll
        for (int i = 0; i < 8; i++) {
            int c = tid + (i << 8); int r = c >> 3, c8 = c & 7;
            uint32_t sf = (uint32_t)(r * 128 + ((c8 * 16) ^ ((r & 7) << 4)));
            cp_async16(sb + OF_A + sf, A + (size_t)(m0 + r) * K + c8 * 8);
        }
        #pragma unroll
        for (int i = 0; i < 2; i++) {
            int c = tid + (i << 8); int r = c >> 3, c8 = c & 7;
            uint32_t sf = (uint32_t)(r * 128 + ((c8 * 16) ^ ((r & 7) << 4)));
            cp_async16(sb + OF_B + sf, B + (size_t)(n0 + r) * K + c8 * 8);
        }
        cp_commit();
    }

    float acc[2][8][4] = {};
    int q = lane >> 3, j = lane & 7;

    for (int s = 0; s < nstages; s++) {
        asm volatile("cp.async.wait_group 0;" ::: "memory");
        __syncthreads();
        if (s + 1 < nstages) {
            uint32_t base = sb + ((s + 1) & 1) * BUF;
            int koff = (s + 1) * 64;
            #pragma unroll
            for (int i = 0; i < 8; i++) {
                int c = tid + (i << 8); int r = c >> 3, c8 = c & 7;
                uint32_t sf = (uint32_t)(r * 128 + ((c8 * 16) ^ ((r & 7) << 4)));
                cp_async16(base + OF_A + sf, A + (size_t)(m0 + r) * K + koff + c8 * 8);
            }
            #pragma unroll
            for (int i = 0; i < 2; i++) {
                int c = tid + (i << 8); int r = c >> 3, c8 = c & 7;
                uint32_t sf = (uint32_t)(r * 128 + ((c8 * 16) ^ ((r & 7) << 4)));
                cp_async16(base + OF_B + sf, B + (size_t)(n0 + r) * K + koff + c8 * 8);
            }
            cp_commit();
        }
        uint32_t base = sb + (s & 1) * BUF;

        #pragma unroll
        for (int kc = 0; kc < 4; kc++) {
            uint32_t bf[4][4];
            #pragma unroll
            for (int np = 0; np < 4; np++) {
                int row = np * 16 + (q >> 1) * 8 + j;
                int cb = kc * 32 + (q & 1) * 16;
                uint32_t so = (uint32_t)(row * 128 + (cb ^ ((row & 7) << 4)));
                ldsm4(bf[np], base + OF_B + so);
            }
            #pragma unroll
            for (int mt = 0; mt < 2; mt++) {
                uint32_t af[4];
                int row = wm * 32 + mt * 16 + (q & 1) * 8 + j;
                int cb = kc * 32 + (q >> 1) * 16;
                uint32_t so = (uint32_t)(row * 128 + (cb ^ ((row & 7) << 4)));
                ldsm4(af, base + OF_A + so);
                #pragma unroll
                for (int nt = 0; nt < 8; nt++) {
                    uint32_t b0 = bf[nt >> 1][(nt & 1) * 2], b1 = bf[nt >> 1][(nt & 1) * 2 + 1];
                    mma16816h(acc[mt][nt], af, b0, b1);
                }
            }
        }
    }

    int r4 = lane >> 2, cg = (lane & 3) * 2;
    #pragma unroll
    for (int mt = 0; mt < 2; mt++) {
        int mrow0 = m0 + wm * 32 + mt * 16 + r4;
        int mrow1 = mrow0 + 8;
        int o0 = scatter ? scatter[mrow0] : mrow0;
        int o1 = scatter ? scatter[mrow1] : mrow1;
        #pragma unroll
        for (int nt = 0; nt < 8; nt++) {
            int col = n0 + nt * 8 + cg;
            float b0 = bias[col], b1 = bias[col + 1];
            float v00 = acc[mt][nt][0] + b0, v01 = acc[mt][nt][1] + b1;
            float v10 = acc[mt][nt][2] + b0, v11 = acc[mt][nt][3] + b1;
            if (EPI == 1) { v00 = gelu_f(v00); v01 = gelu_f(v01); v10 = gelu_f(v10); v11 = gelu_f(v11); }
            *reinterpret_cast<uint32_t*>(outH + (size_t)o0 * Nn + col) =
                (uint32_t)h16(v00) | ((uint32_t)h16(v01) << 16);
            *reinterpret_cast<uint32_t*>(outH + (size_t)o1 * Nn + col) =
                (uint32_t)h16(v10) | ((uint32_t)h16(v11) << 16);
        }
    }
}

// ========= fused out-proj GEMM (64x192 tile) + add + LayerNorm epilogue =========
__global__ void __launch_bounds__(256, 2)
gemm_oproj_ln(const __half* __restrict__ A, const __half* __restrict__ B,
              const float* __restrict__ bias, const int* __restrict__ inds,
              const __half* __restrict__ Xf,
              const float* __restrict__ lng, const float* __restrict__ lnb,
              __half* __restrict__ X1f) {
    extern __shared__ char smem[];
    const int BUF = 32768;
    const int OF_A = 0, OF_B = 8192;
    uint32_t sb = smem_u32(smem);
    int tid = threadIdx.x, wid = tid >> 5, lane = tid & 31;
    int m0 = blockIdx.x * 64;
    int gq = wid >> 1, wn = wid & 1;

    const int K = CD;
    const int nstages = 3;

    {
        #pragma unroll
        for (int i = 0; i < 2; i++) {
            int c = tid + (i << 8); int r = c >> 3, c8 = c & 7;
            uint32_t sf = (uint32_t)(r * 128 + ((c8 * 16) ^ ((r & 7) << 4)));
            cp_async16(sb + OF_A + sf, A + (size_t)(m0 + r) * K + c8 * 8);
        }
        #pragma unroll
        for (int i = 0; i < 6; i++) {
            int c = tid + (i << 8); int r = c >> 3, c8 = c & 7;
            uint32_t sf = (uint32_t)(r * 128 + ((c8 * 16) ^ ((r & 7) << 4)));
            cp_async16(sb + OF_B + sf, B + (size_t)r * K + c8 * 8);
        }
        cp_commit();
    }

    float acc[12][4] = {};
    int q = lane >> 3, j = lane & 7;

    for (int s = 0; s < nstages; s++) {
        asm volatile("cp.async.wait_group 0;" ::: "memory");
        __syncthreads();
        if (s + 1 < nstages) {
            uint32_t base = sb + ((s + 1) & 1) * BUF;
            int koff = (s + 1) * 64;
            #pragma unroll
            for (int i = 0; i < 2; i++) {
                int c = tid + (i << 8); int r = c >> 3, c8 = c & 7;
                uint32_t sf = (uint32_t)(r * 128 + ((c8 * 16) ^ ((r & 7) << 4)));
                cp_async16(base + OF_A + sf, A + (size_t)(m0 + r) * K + koff + c8 * 8);
            }
            #pragma unroll
            for (int i = 0; i < 6; i++) {
                int c = tid + (i << 8); int r = c >> 3, c8 = c & 7;
                uint32_t sf = (uint32_t)(r * 128 + ((c8 * 16) ^ ((r & 7) << 4)));
                cp_async16(base + OF_B + sf, B + (size_t)r * K + koff + c8 * 8);
            }
            cp_commit();
        }
        uint32_t base = sb + (s & 1) * BUF;

        #pragma unroll
        for (int kc = 0; kc < 4; kc++) {
            uint32_t af[4];
            {
                int row = gq * 16 + (q & 1) * 8 + j;
                int cb = kc * 32 + (q >> 1) * 16;
                uint32_t so = (uint32_t)(row * 128 + (cb ^ ((row & 7) << 4)));
                ldsm4(af, base + OF_A + so);
            }
            #pragma unroll
            for (int np = 0; np < 6; np++) {
                uint32_t bf[4];
                int row = wn * 96 + np * 16 + (q >> 1) * 8 + j;
                int cb = kc * 32 + (q & 1) * 16;
                uint32_t so = (uint32_t)(row * 128 + (cb ^ ((row & 7) << 4)));
                ldsm4(bf, base + OF_B + so);
                mma16816h(acc[np * 2 + 0], af, bf[0], bf[1]);
                mma16816h(acc[np * 2 + 1], af, bf[2], bf[3]);
            }
        }
    }

    int r4 = lane >> 2, cg = (lane & 3) * 2;
    int lrowA = gq * 16 + r4, lrowB = lrowA + 8;
    int oA = inds[m0 + lrowA], oB = inds[m0 + lrowB];

    float sA = 0.f, s2A = 0.f, sB = 0.f, s2B = 0.f;
    #pragma unroll
    for (int nt = 0; nt < 12; nt++) {
        int col = wn * 96 + nt * 8 + cg;
        float b0 = bias[col], b1 = bias[col + 1];
        float2 xA = h2f2u(*reinterpret_cast<const uint32_t*>(Xf + (size_t)oA * CD + col));
        float2 xB = h2f2u(*reinterpret_cast<const uint32_t*>(Xf + (size_t)oB * CD + col));
        float v0 = acc[nt][0] + b0 + xA.x, v1 = acc[nt][1] + b1 + xA.y;
        float v2 = acc[nt][2] + b0 + xB.x, v3 = acc[nt][3] + b1 + xB.y;
        acc[nt][0] = v0; acc[nt][1] = v1; acc[nt][2] = v2; acc[nt][3] = v3;
        sA += v0 + v1; s2A += v0 * v0 + v1 * v1;
        sB += v2 + v3; s2B += v2 * v2 + v3 * v3;
    }
    #pragma unroll
    for (int o = 1; o <= 2; o <<= 1) {
        sA  += __shfl_xor_sync(0xffffffffu, sA,  o);
        s2A += __shfl_xor_sync(0xffffffffu, s2A, o);
        sB  += __shfl_xor_sync(0xffffffffu, sB,  o);
        s2B += __shfl_xor_sync(0xffffffffu, s2B, o);
    }
    float* red = reinterpret_cast<float*>(smem);
    __syncthreads();
    if ((lane & 3) == 0) {
        red[(wn * 64 + lrowA) * 2 + 0] = sA;
        red[(wn * 64 + lrowA) * 2 + 1] = s2A;
        red[(wn * 64 + lrowB) * 2 + 0] = sB;
        red[(wn * 64 + lrowB) * 2 + 1] = s2B;
    }
    __syncthreads();
    float tsA  = red[lrowA * 2 + 0] + red[(64 + lrowA) * 2 + 0];
    float ts2A = red[lrowA * 2 + 1] + red[(64 + lrowA) * 2 + 1];
    float tsB  = red[lrowB * 2 + 0] + red[(64 + lrowB) * 2 + 0];
    float ts2B = red[lrowB * 2 + 1] + red[(64 + lrowB) * 2 + 1];
    float mA = tsA * (1.0f / CD), vA = ts2A * (1.0f / CD) - mA * mA;
    float mB = tsB * (1.0f / CD), vB = ts2B * (1.0f / CD) - mB * mB;
    float rA = rsqrtf(vA + 1e-5f), rB = rsqrtf(vB + 1e-5f);

    #pragma unroll
    for (int nt = 0; nt < 12; nt++) {
        int col = wn * 96 + nt * 8 + cg;
        float g0 = lng[col], g1 = lng[col + 1];
        float bb0 = lnb[col], bb1 = lnb[col + 1];
        float y0 = (acc[nt][0] - mA) * rA * g0 + bb0;
        float y1 = (acc[nt][1] - mA) * rA * g1 + bb1;
        float y2 = (acc[nt][2] - mB) * rB * g0 + bb0;
        float y3 = (acc[nt][3] - mB) * rB * g1 + bb1;
        *reinterpret_cast<uint32_t*>(X1f + (size_t)oA * CD + col) =
            (uint32_t)h16(y0) | ((uint32_t)h16(y1) << 16);
        *reinterpret_cast<uint32_t*>(X1f + (size_t)oB * CD + col) =
            (uint32_t)h16(y2) | ((uint32_t)h16(y3) << 16);
    }
}

// ===== per (set, head) attention — R12 version (4r x 1l broadcast QK) =====
#define DP 28
__global__ void __launch_bounds__(128)
attn_k(const __half* __restrict__ QKV, __half* __restrict__ AOf) {
    int s = blockIdx.x, h = blockIdx.y;
    __shared__ float q[SETK][DP], k[SETK][DP], v[SETK][DP];
    __shared__ float sc[SETK][SETK];
    int tid = threadIdx.x;
    const __half* base = QKV + (size_t)s * SETK * (3 * CD) + h * DHD;
    for (int t = tid; t < SETK * 6; t += 128) {
        int r = t / 6, c4 = t - r * 6;
        const __half* rp = base + r * (3 * CD) + c4 * 4;
        const __half2* qp = reinterpret_cast<const __half2*>(rp);
        const __half2* kp = reinterpret_cast<const __half2*>(rp + CD);
        const __half2* vp = reinterpret_cast<const __half2*>(rp + 2 * CD);
        float2 a0 = __half22float2(qp[0]), a1 = __half22float2(qp[1]);
        q[r][c4*4+0] = a0.x; q[r][c4*4+1] = a0.y; q[r][c4*4+2] = a1.x; q[r][c4*4+3] = a1.y;
        float2 b0 = __half22float2(kp[0]), b1 = __half22float2(kp[1]);
        k[r][c4*4+0] = b0.x; k[r][c4*4+1] = b0.y; k[r][c4*4+2] = b1.x; k[r][c4*4+3] = b1.y;
        float2 c0 = __half22float2(vp[0]), c1 = __half22float2(vp[1]);
        v[r][c4*4+0] = c0.x; v[r][c4*4+1] = c0.y; v[r][c4*4+2] = c1.x; v[r][c4*4+3] = c1.y;
    }
    __syncthreads();
    const float scale = 0.20412414523193150818f;
    for (int u = tid; u < 9 * SETK; u += 128) {
        int rq = u / SETK, l = u - rq * SETK;
        int r0 = rq * 4;
        float a0 = 0.f, a1 = 0.f, a2 = 0.f, a3 = 0.f;
        #pragma unroll
        for (int c4 = 0; c4 < 6; c4++) {
            float4 b  = *reinterpret_cast<const float4*>(&k[l][c4 * 4]);
            float4 q0 = *reinterpret_cast<const float4*>(&q[r0 + 0][c4 * 4]);
            float4 q1 = *reinterpret_cast<const float4*>(&q[r0 + 1][c4 * 4]);
            float4 q2 = *reinterpret_cast<const float4*>(&q[r0 + 2][c4 * 4]);
            float4 q3 = *reinterpret_cast<const float4*>(&q[r0 + 3][c4 * 4]);
            a0 = fmaf(q0.x, b.x, a0); a0 = fmaf(q0.y, b.y, a0);
            a0 = fmaf(q0.z, b.z, a0); a0 = fmaf(q0.w, b.w, a0);
            a1 = fmaf(q1.x, b.x, a1); a1 = fmaf(q1.y, b.y, a1);
            a1 = fmaf(q1.z, b.z, a1); a1 = fmaf(q1.w, b.w, a1);
            a2 = fmaf(q2.x, b.x, a2); a2 = fmaf(q2.y, b.y, a2);
            a2 = fmaf(q2.z, b.z, a2); a2 = fmaf(q2.w, b.w, a2);
            a3 = fmaf(q3.x, b.x, a3); a3 = fmaf(q3.y, b.y, a3);
            a3 = fmaf(q3.z, b.z, a3); a3 = fmaf(q3.w, b.w, a3);
        }
        sc[r0 + 0][l] = a0 * scale;
        sc[r0 + 1][l] = a1 * scale;
        sc[r0 + 2][l] = a2 * scale;
        sc[r0 + 3][l] = a3 * scale;
    }
    __syncthreads();
    if (tid < SETK) {
        int r = tid;
        float4 rowv[9];
        #pragma unroll
        for (int i = 0; i < 9; i++) rowv[i] = *reinterpret_cast<const float4*>(&sc[r][i * 4]);
        float mx = -1e30f;
        #pragma unroll
        for (int i = 0; i < 9; i++)
            mx = fmaxf(mx, fmaxf(fmaxf(rowv[i].x, rowv[i].y), fmaxf(rowv[i].z, rowv[i].w)));
        float sum = 0.f;
        #pragma unroll
        for (int i = 0; i < 9; i++) {
            rowv[i].x = expf(rowv[i].x - mx); rowv[i].y = expf(rowv[i].y - mx);
            rowv[i].z = expf(rowv[i].z - mx); rowv[i].w = expf(rowv[i].w - mx);
            sum += rowv[i].x + rowv[i].y + rowv[i].z + rowv[i].w;
        }
        float inv = 1.0f / sum;
        #pragma unroll
        for (int i = 0; i < 9; i++) {
            rowv[i].x *= inv; rowv[i].y *= inv; rowv[i].z *= inv; rowv[i].w *= inv;
            *reinterpret_cast<float4*>(&sc[r][i * 4]) = rowv[i];
        }
    }
    __syncthreads();
    for (int u = tid; u < SETK * 6; u += 128) {
        int r = u / 6, c4 = u - r * 6;
        float4 acc = make_float4(0.f, 0.f, 0.f, 0.f);
        #pragma unroll 4
        for (int l = 0; l < SETK; l++) {
            float w = sc[r][l];
            float4 vv = *reinterpret_cast<const float4*>(&v[l][c4 * 4]);
            acc.x = fmaf(w, vv.x, acc.x); acc.y = fmaf(w, vv.y, acc.y);
            acc.z = fmaf(w, vv.z, acc.z); acc.w = fmaf(w, vv.w, acc.w);
        }
        size_t ob = (size_t)(s * SETK + r) * CD + h * DHD + c4 * 4;
        *reinterpret_cast<uint2*>(AOf + ob) =
            make_uint2((uint32_t)h16(acc.x) | ((uint32_t)h16(acc.y) << 16),
                       (uint32_t)h16(acc.z) | ((uint32_t)h16(acc.w) << 16));
    }
}

// ================= warp LayerNorm (lane -> 6 consecutive cols) =================
__device__ __forceinline__ void warp_ln6c(float (&x)[6], const float* __restrict__ g,
                                          const float* __restrict__ b, int cbase, float (&y)[6]) {
    float s = 0.f, s2 = 0.f;
    #pragma unroll
    for (int j = 0; j < 6; j++) { s += x[j]; s2 += x[j] * x[j]; }
    #pragma unroll
    for (int o = 16; o > 0; o >>= 1) {
        s  += __shfl_xor_sync(0xffffffffu, s, o);
        s2 += __shfl_xor_sync(0xffffffffu, s2, o);
    }
    float mean = s * (1.0f / CD);
    float var  = s2 * (1.0f / CD) - mean * mean;
    float r = rsqrtf(var + 1e-5f);
    #pragma unroll
    for (int j = 0; j < 6; j++)
        y[j] = (x[j] - mean) * r * g[cbase + j] + b[cbase + j];
}
__device__ __forceinline__ void load6(const float* p, float (&x)[6]) {
    float2 a = *reinterpret_cast<const float2*>(p);
    float2 b = *reinterpret_cast<const float2*>(p + 2);
    float2 c = *reinterpret_cast<const float2*>(p + 4);
    x[0]=a.x; x[1]=a.y; x[2]=b.x; x[3]=b.y; x[4]=c.x; x[5]=c.y;
}
__device__ __forceinline__ void load6h(const __half* p, float (&x)[6]) {
    const __half2* hp = reinterpret_cast<const __half2*>(p);
    float2 a = __half22float2(hp[0]);
    float2 b = __half22float2(hp[1]);
    float2 c = __half22float2(hp[2]);
    x[0]=a.x; x[1]=a.y; x[2]=b.x; x[3]=b.y; x[4]=c.x; x[5]=c.y;
}
__device__ __forceinline__ void store6(float* p, const float (&y)[6]) {
    *reinterpret_cast<float2*>(p)     = make_float2(y[0], y[1]);
    *reinterpret_cast<float2*>(p + 2) = make_float2(y[2], y[3]);
    *reinterpret_cast<float2*>(p + 4) = make_float2(y[4], y[5]);
}
__device__ __forceinline__ void store6_h(__half* ph, const float (&y)[6]) {
    *reinterpret_cast<uint32_t*>(ph)     = (uint32_t)h16(y[0]) | ((uint32_t)h16(y[1]) << 16);
    *reinterpret_cast<uint32_t*>(ph + 2) = (uint32_t)h16(y[2]) | ((uint32_t)h16(y[3]) << 16);
    *reinterpret_cast<uint32_t*>(ph + 4) = (uint32_t)h16(y[4]) | ((uint32_t)h16(y[5]) << 16);
}

// LN chain: all activation streams fp16; out = fp32 (last layer) or fp16 Xf
__global__ void __launch_bounds__(256)
fused_ln3_k(const __half* __restrict__ X1f, const __half* __restrict__ FOf,
            const __half* __restrict__ IDf, const __half* __restrict__ RESf,
            const float* __restrict__ g2, const float* __restrict__ b2,
            const float* __restrict__ ge, const float* __restrict__ be,
            const float* __restrict__ gb, const float* __restrict__ bb,
            float* __restrict__ outF, __half* __restrict__ outXf,
            __half* __restrict__ Rdst,
            const float* __restrict__ posn, const int* __restrict__ invn,
            __half* __restrict__ Gf, __half* __restrict__ Qf) {
    int row = blockIdx.x * blockDim.y + threadIdx.y;
    int cbase = threadIdx.x * 6;
    size_t off = (size_t)row * CD + cbase;
    float x[6], t[6], y[6];
    load6h(X1f + off, x); load6h(FOf + off, t);
    #pragma unroll
    for (int j = 0; j < 6; j++) x[j] += t[j];
    warp_ln6c(x, g2, b2, cbase, y);
    load6h(IDf + off, t);
    #pragma unroll
    for (int j = 0; j < 6; j++) x[j] = y[j] + t[j];
    warp_ln6c(x, ge, be, cbase, y);
    if (RESf) {
        load6h(RESf + off, t);
        #pragma unroll
        for (int j = 0; j < 6; j++) x[j] = y[j] + t[j];
        warp_ln6c(x, gb, bb, cbase, y);
    }
    if (outF) store6(outF + off, y);
    if (outXf) store6_h(outXf + off, y);
    if (Rdst) store6_h(Rdst + off, y);
    if (Gf) {
        int p = invn[row];
        size_t soff = (size_t)p * CD + cbase;
        store6_h(Gf + soff, y);
        float q[6];
        load6(posn + off, t);
        #pragma unroll
        for (int j = 0; j < 6; j++) q[j] = y[j] + t[j];
        store6_h(Qf + soff, q);
    }
}

// ================= host =================
extern "C" void kernel_launch(void* const* d_in, const int* in_sizes, int n_in,
                              void* d_out, int out_size) {
    const float* src       = (const float*)d_in[0];
    const float* pos_embed = (const float*)d_in[1];
    const int*   svi       = (const int*)  d_in[2];
    const float* in_proj_w = (const float*)d_in[4];
    const float* in_proj_b = (const float*)d_in[5];
    const float* out_w     = (const float*)d_in[6];
    const float* out_b     = (const float*)d_in[7];
    const float* lin1_w    = (const float*)d_in[8];
    const float* lin1_b    = (const float*)d_in[9];
    const float* lin2_w    = (const float*)d_in[10];
    const float* lin2_b    = (const float*)d_in[11];
    const float* ln1_g     = (const float*)d_in[12];
    const float* ln1_b     = (const float*)d_in[13];
    const float* ln2_g     = (const float*)d_in[14];
    const float* ln2_b     = (const float*)d_in[15];
    const float* enc_g     = (const float*)d_in[16];
    const float* enc_b     = (const float*)d_in[17];
    const float* blk_g     = (const float*)d_in[18];
    const float* blk_b     = (const float*)d_in[19];
    float* outp = (float*)d_out;

    int *INV;
    __half *Xf, *Rf, *QKVh, *FOf, *Gf, *Qf, *AOf, *X1f, *Hf;
    __half *W0, *W1, *W2, *W3;
    cudaGetSymbolAddress((void**)&Xf,   g_Xf);   cudaGetSymbolAddress((void**)&Rf,  g_Rf);
    cudaGetSymbolAddress((void**)&INV,  g_INV);
    cudaGetSymbolAddress((void**)&QKVh, g_QKVh); cudaGetSymbolAddress((void**)&FOf, g_FOf);
    cudaGetSymbolAddress((void**)&Gf,   g_Gf);   cudaGetSymbolAddress((void**)&Qf,  g_Qf);
    cudaGetSymbolAddress((void**)&AOf,  g_AOf);  cudaGetSymbolAddress((void**)&X1f, g_X1f);
    cudaGetSymbolAddress((void**)&Hf,   g_Hf);
    cudaGetSymbolAddress((void**)&W0,   g_W0);   cudaGetSymbolAddress((void**)&W1,  g_W1);
    cudaGetSymbolAddress((void**)&W2,   g_W2);   cudaGetSymbolAddress((void**)&W3,  g_W3);

    const int SMEM_GEMM = 81920;
    const int SMEM_OPLN = 65536;
    cudaFuncSetAttribute(gemm_mma<0>, cudaFuncAttributeMaxDynamicSharedMemorySize, SMEM_GEMM);
    cudaFuncSetAttribute(gemm_mma<1>, cudaFuncAttributeMaxDynamicSharedMemorySize, SMEM_GEMM);
    cudaFuncSetAttribute(gemm_oproj_ln, cudaFuncAttributeMaxDynamicSharedMemorySize, SMEM_OPLN);

    const size_t NC = (size_t)NV * CD;

    int totW = W0SZ + W1SZ + W2SZ + W3SZ;
    convw_k<<<(totW + 255) / 256, 256>>>(in_proj_w, out_w, lin1_w, lin2_w, W0, W1, W2, W3);
    invperm_k<<<(4 * NV + 255) / 256, 256>>>(svi, INV);
    int cvBlocks = (NV * (CD / 4) + 255) / 256;
    convsrc_k<<<cvBlocks, 256>>>(src, Xf, Rf);

    dim3 lnGrid(NV / 8), lnBlk(32, 8);
    gather_k<<<cvBlocks, 256>>>(src, pos_embed, svi, Gf, Qf);

    const int MB = NV / 256;   // 288 M-tiles

    for (int blk = 0; blk < 4; blk++) {
        int shift = blk & 1;
        for (int i = 0; i < 2; i++) {
            int li = blk * 2 + i;
            const int* inds = svi + (size_t)(shift * 2 + i) * SETN * SETK;

            // QKV: cols [0,384) from Q-input, cols [384,576) from G
            gemm_mma<0><<<dim3(9, MB), 256, SMEM_GEMM>>>(
                Qf, Gf, 384,
                W0 + (size_t)li * 3 * CD * CD, in_proj_b + (size_t)li * 3 * CD,
                QKVh, nullptr, 3 * CD, CD);

            attn_k<<<dim3(SETN, HD), 128>>>(QKVh, AOf);

            // out-proj + scatter + add + LN1 (fused) -> X1f only
            gemm_oproj_ln<<<NV / 64, 256, SMEM_OPLN>>>(
                AOf, W1 + (size_t)li * CD * CD, out_b + (size_t)li * CD,
                inds, Xf, ln1_g + li * CD, ln1_b + li * CD, X1f);

            // ffn1 + gelu
            gemm_mma<1><<<dim3(6, MB), 256, SMEM_GEMM>>>(
                X1f, X1f, 1 << 30,
                W2 + (size_t)li * FF * CD, lin1_b + (size_t)li * FF,
                Hf, nullptr, FF, CD);

            // ffn2
            gemm_mma<0><<<dim3(3, MB), 256, SMEM_GEMM>>>(
                Hf, Hf, 1 << 30,
                W3 + (size_t)li * CD * FF, lin2_b + (size_t)li * CD,
                FOf, nullptr, CD, FF);

            bool blockEnd = (i == 1);
            bool last = (li == NLAYER - 1);
            const float* posn = nullptr; const int* invn = nullptr;
            __half *gf = nullptr, *qf = nullptr;
            if (!last) {
                int lnx = li + 1;
                int pn = ((lnx / 2) & 1) * 2 + (lnx & 1);
                posn = pos_embed + (size_t)(lnx & 1) * NC;
                invn = INV + (size_t)pn * NV;
                gf = Gf; qf = Qf;
            }
            fused_ln3_k<<<lnGrid, lnBlk>>>(
                X1f, FOf, Xf, blockEnd ? Rf : nullptr,
                ln2_g + li * CD, ln2_b + li * CD,
                enc_g + li * CD, enc_b + li * CD,
                blk_g + blk * CD, blk_b + blk * CD,
                last ? outp : nullptr, last ? nullptr : Xf,
                (blockEnd && !last) ? Rf : nullptr,
                posn, invn, gf, qf);
        }
    }
}